// round 8
// baseline (speedup 1.0000x reference)
#include <cuda_runtime.h>
#include <cuda_bf16.h>
#include <cuda_fp16.h>
#include <cstdint>

#define N_IMG 8192
#define N_TXT 8192
#define DIM   1024
#define HDIM  1024

typedef __nv_bfloat16 bf16;

// ---------------------------------------------------------------------------
// Device scratch (no allocations allowed)
// ---------------------------------------------------------------------------
__device__ __align__(1024) __half g_img16[(size_t)N_IMG * DIM];
__device__ __align__(1024) __half g_txt16[(size_t)N_TXT * DIM];
__device__ __align__(1024) __half g_wq16 [(size_t)HDIM * DIM];
__device__ __align__(1024) __half g_wk16 [(size_t)HDIM * DIM];
__device__ __align__(1024) bf16 g_txth[(size_t)N_TXT * DIM], g_txtl[(size_t)N_TXT * DIM];
__device__ __align__(1024) bf16 g_wvh [(size_t)DIM * DIM],   g_wvl [(size_t)DIM * DIM];
__device__ __align__(1024) __half g_q16 [(size_t)N_IMG * HDIM];
__device__ __align__(1024) __half g_k16 [(size_t)N_TXT * HDIM];
__device__ __align__(1024) __half g_vt16[(size_t)DIM * N_TXT];
__device__ __align__(1024) __half g_p16 [(size_t)N_IMG * N_TXT];   // 128 MB
__device__ __align__(1024) float  g_pvs [2 * (size_t)N_IMG * DIM]; // 64 MB split-K partials
__device__ __align__(1024) float  g_rowsum[N_IMG];

// exp constants: exp(s*0.03125 - 8) = exp2(acc*c1 + c2)
#define EXP_C1 0.04508422f      // 0.03125 * log2(e)
#define EXP_C2 -11.54156036f    // -8 * log2(e)

// ---------------------------------------------------------------------------
// Portable PTX helpers
// ---------------------------------------------------------------------------
__device__ __forceinline__ uint32_t smem_to_u32(const void* p) {
    uint32_t a;
    asm("{ .reg .u64 t; cvta.to.shared.u64 t, %1; cvt.u32.u64 %0, t; }" : "=r"(a) : "l"(p));
    return a;
}
__device__ __forceinline__ void ldmatrix_x4(uint32_t* r, uint32_t addr) {
    asm volatile("ldmatrix.sync.aligned.m8n8.x4.shared.b16 {%0,%1,%2,%3}, [%4];"
        : "=r"(r[0]), "=r"(r[1]), "=r"(r[2]), "=r"(r[3]) : "r"(addr));
}
__device__ __forceinline__ void mma_bf16(float* c, const uint32_t* a, uint32_t b0, uint32_t b1) {
    asm volatile("mma.sync.aligned.m16n8k16.row.col.f32.bf16.bf16.f32 "
        "{%0,%1,%2,%3}, {%4,%5,%6,%7}, {%8,%9}, {%0,%1,%2,%3};"
        : "+f"(c[0]), "+f"(c[1]), "+f"(c[2]), "+f"(c[3])
        : "r"(a[0]), "r"(a[1]), "r"(a[2]), "r"(a[3]), "r"(b0), "r"(b1));
}
__device__ __forceinline__ void mma_fp16(float* c, const uint32_t* a, uint32_t b0, uint32_t b1) {
    asm volatile("mma.sync.aligned.m16n8k16.row.col.f32.f16.f16.f32 "
        "{%0,%1,%2,%3}, {%4,%5,%6,%7}, {%8,%9}, {%0,%1,%2,%3};"
        : "+f"(c[0]), "+f"(c[1]), "+f"(c[2]), "+f"(c[3])
        : "r"(a[0]), "r"(a[1]), "r"(a[2]), "r"(a[3]), "r"(b0), "r"(b1));
}
#define CP_ASYNC16(dst, src) \
    asm volatile("cp.async.cg.shared.global [%0], [%1], 16;" :: "r"(dst), "l"(src) : "memory")
#define CP_COMMIT() asm volatile("cp.async.commit_group;" ::: "memory")
#define CP_WAIT1()  asm volatile("cp.async.wait_group 1;" ::: "memory")

// ===========================================================================
// Kernel 1: 3-term compensated bf16 GEMM — V projection (accuracy path)
// ===========================================================================
constexpr int TILE_B = 8192;
constexpr int OFF_AH = 0, OFF_AL = TILE_B, OFF_BH = 2 * TILE_B, OFF_BL = 3 * TILE_B;
constexpr int STG = 4 * TILE_B;
constexpr int NSTAGE = 3;
constexpr int GEMM_SMEM = NSTAGE * STG;      // 96 KB

__device__ __forceinline__ void load_tile32(uint32_t dst, const bf16* __restrict__ src,
                                            int ldK, int tid) {
#pragma unroll
    for (int i = 0; i < 2; i++) {
        int idx = tid + i * 256;
        int r = idx >> 2, c = idx & 3;
        int sc = c ^ ((r >> 1) & 3);
        CP_ASYNC16(dst + r * 64 + (sc << 4), src + (size_t)r * ldK + c * 8);
    }
}

__global__ void __launch_bounds__(256, 1)
proj_gemm(const bf16* __restrict__ Ahi, const bf16* __restrict__ Alo,
          const bf16* __restrict__ Bhi, const bf16* __restrict__ Blo,
          __half* __restrict__ C, int M, int N, int K)
{
    extern __shared__ __align__(1024) char smem[];
    const uint32_t sb = smem_to_u32(smem);
    const int tid  = threadIdx.x;
    const int lane = tid & 31;
    const int wid  = tid >> 5;
    const int wm   = wid & 1;
    const int wn   = wid >> 1;
    const int m0   = blockIdx.y * 128, n0 = blockIdx.x * 128;

    const bf16* Ah = Ahi + (size_t)m0 * K;
    const bf16* Al = Alo + (size_t)m0 * K;
    const bf16* Bh = Bhi + (size_t)n0 * K;
    const bf16* Bl = Blo + (size_t)n0 * K;

    float acc[4][4][4];
#pragma unroll
    for (int i = 0; i < 4; i++)
#pragma unroll
        for (int j = 0; j < 4; j++)
#pragma unroll
            for (int t = 0; t < 4; t++) acc[i][j][t] = 0.f;

    const int NK = K >> 5;

#pragma unroll
    for (int i = 0; i < NSTAGE - 1; i++) {
        if (i < NK) {
            uint32_t st = sb + i * STG;
            int ko = i * 32;
            load_tile32(st + OFF_AH, Ah + ko, K, tid);
            load_tile32(st + OFF_AL, Al + ko, K, tid);
            load_tile32(st + OFF_BH, Bh + ko, K, tid);
            load_tile32(st + OFF_BL, Bl + ko, K, tid);
        }
        CP_COMMIT();
    }

    const int lr = lane & 15;
    const int lc = lane >> 4;

    for (int k = 0; k < NK; k++) {
        CP_WAIT1();
        __syncthreads();

        int kn = k + NSTAGE - 1;
        if (kn < NK) {
            uint32_t st = sb + (kn % NSTAGE) * STG;
            int ko = kn * 32;
            load_tile32(st + OFF_AH, Ah + ko, K, tid);
            load_tile32(st + OFF_AL, Al + ko, K, tid);
            load_tile32(st + OFF_BH, Bh + ko, K, tid);
            load_tile32(st + OFF_BL, Bl + ko, K, tid);
        }
        CP_COMMIT();

        const uint32_t s = sb + (k % NSTAGE) * STG;
#pragma unroll
        for (int ks = 0; ks < 2; ks++) {
            uint32_t ah[4][4], al[4][4], bh[2][4], bl[2][4];
#pragma unroll
            for (int mi = 0; mi < 4; mi++) {
                int r = wm * 64 + mi * 16 + lr;
                int c = ks * 2 + lc;
                int sc = c ^ ((r >> 1) & 3);
                uint32_t a = s + r * 64 + (sc << 4);
                ldmatrix_x4(ah[mi], a + OFF_AH);
                ldmatrix_x4(al[mi], a + OFF_AL);
            }
#pragma unroll
            for (int nj = 0; nj < 2; nj++) {
                int r = wn * 32 + nj * 16 + lr;
                int c = ks * 2 + lc;
                int sc = c ^ ((r >> 1) & 3);
                uint32_t a = s + r * 64 + (sc << 4);
                ldmatrix_x4(bh[nj], a + OFF_BH);
                ldmatrix_x4(bl[nj], a + OFF_BL);
            }
#pragma unroll
            for (int mi = 0; mi < 4; mi++)
#pragma unroll
                for (int ni = 0; ni < 4; ni++) {
                    int nj = ni >> 1, hl = ni & 1;
                    mma_bf16(acc[mi][ni], ah[mi], bh[nj][hl], bh[nj][2 + hl]);
                    mma_bf16(acc[mi][ni], ah[mi], bl[nj][hl], bl[nj][2 + hl]);
                    mma_bf16(acc[mi][ni], al[mi], bh[nj][hl], bh[nj][2 + hl]);
                }
        }
    }

    const int er = (lane >> 2);
    const int ec = (lane & 3) * 2;
#pragma unroll
    for (int mi = 0; mi < 4; mi++)
#pragma unroll
        for (int ni = 0; ni < 4; ni++) {
            int row = m0 + wm * 64 + mi * 16 + er;
            int col = n0 + wn * 32 + ni * 8 + ec;
#pragma unroll
            for (int h = 0; h < 2; h++) {
                float v0 = acc[mi][ni][2 * h + 0];
                float v1 = acc[mi][ni][2 * h + 1];
                size_t off = (size_t)(row + 8 * h) * N + col;
                *reinterpret_cast<__half2*>(C + off) = __floats2half2_rn(v0, v1);
            }
        }
}

// ===========================================================================
// Kernel 2: single-term fp16 GEMM, epilogue modes:
//   MODE 1: C fp16; dual operand sets selected by blockIdx.z (merged Q+K proj)
//   MODE 2: C fp16 = exp2(acc*EXP_C1 + EXP_C2) + rowsum atomics  (QK^T)
//   MODE 4: C fp32 plain, split-K by blockIdx.z into disjoint partials (PV)
// ===========================================================================
constexpr int H_TILE = 16384;
constexpr int H_OFF_A = 0, H_OFF_B = H_TILE;
constexpr int H_STG = 2 * H_TILE;
constexpr int H_NSTAGE = 3;
constexpr int H_SMEM = H_NSTAGE * H_STG;     // 96 KB

__device__ __forceinline__ void load_tile64h(uint32_t dst, const __half* __restrict__ src,
                                             int ld, int tid) {
#pragma unroll
    for (int i = 0; i < 4; i++) {
        int idx = tid + i * 256;
        int r = idx >> 3, c = idx & 7;
        int sc = c ^ (r & 7);
        CP_ASYNC16(dst + r * 128 + (sc << 4), src + (size_t)r * ld + c * 8);
    }
}

template <int MODE>
__global__ void __launch_bounds__(256, 1)
hgemm(const __half* __restrict__ A, const __half* __restrict__ B,
      float* __restrict__ Cf, __half* __restrict__ Ch,
      float* __restrict__ rowsum,
      const __half* __restrict__ A2, const __half* __restrict__ B2,
      __half* __restrict__ Ch2,
      int M, int N, int K, int lda, int ldb)
{
    extern __shared__ __align__(1024) char smem[];
    const uint32_t sb = smem_to_u32(smem);
    const int tid  = threadIdx.x;
    const int lane = tid & 31;
    const int wid  = tid >> 5;
    const int wm   = wid & 1;
    const int wn   = wid >> 1;
    const int m0   = blockIdx.y * 128, n0 = blockIdx.x * 128;
    const int zz   = blockIdx.z;

    const __half* Abase = A;
    const __half* Bbase = B;
    __half* ChU = Ch;
    float*  CfU = Cf;
    if (MODE == 1 && zz == 1) { Abase = A2; Bbase = B2; ChU = Ch2; }
    if (MODE == 4) {           // split-K: z picks K-half and partial buffer
        Abase = A + (size_t)zz * K;      // column offset within lda-stride rows
        Bbase = B + (size_t)zz * K;
        CfU   = Cf + (size_t)zz * M * N;
    }

    const __half* Ar = Abase + (size_t)m0 * lda;
    const __half* Br = Bbase + (size_t)n0 * ldb;

    float acc[4][4][4];
#pragma unroll
    for (int i = 0; i < 4; i++)
#pragma unroll
        for (int j = 0; j < 4; j++)
#pragma unroll
            for (int t = 0; t < 4; t++) acc[i][j][t] = 0.f;

    const int NK = K >> 6;

#pragma unroll
    for (int i = 0; i < H_NSTAGE - 1; i++) {
        if (i < NK) {
            uint32_t st = sb + i * H_STG;
            int ko = i * 64;
            load_tile64h(st + H_OFF_A, Ar + ko, lda, tid);
            load_tile64h(st + H_OFF_B, Br + ko, ldb, tid);
        }
        CP_COMMIT();
    }

    const int lr = lane & 15;
    const int lc = lane >> 4;

    for (int k = 0; k < NK; k++) {
        CP_WAIT1();
        __syncthreads();

        int kn = k + H_NSTAGE - 1;
        if (kn < NK) {
            uint32_t st = sb + (kn % H_NSTAGE) * H_STG;
            int ko = kn * 64;
            load_tile64h(st + H_OFF_A, Ar + ko, lda, tid);
            load_tile64h(st + H_OFF_B, Br + ko, ldb, tid);
        }
        CP_COMMIT();

        const uint32_t s = sb + (k % H_NSTAGE) * H_STG;
#pragma unroll
        for (int ks = 0; ks < 4; ks++) {
            uint32_t af[4][4], bfr[2][4];
#pragma unroll
            for (int mi = 0; mi < 4; mi++) {
                int r = wm * 64 + mi * 16 + lr;
                int c = ks * 2 + lc;
                int sc = c ^ (r & 7);
                ldmatrix_x4(af[mi], s + H_OFF_A + r * 128 + (sc << 4));
            }
#pragma unroll
            for (int nj = 0; nj < 2; nj++) {
                int r = wn * 32 + nj * 16 + lr;
                int c = ks * 2 + lc;
                int sc = c ^ (r & 7);
                ldmatrix_x4(bfr[nj], s + H_OFF_B + r * 128 + (sc << 4));
            }
#pragma unroll
            for (int mi = 0; mi < 4; mi++)
#pragma unroll
                for (int ni = 0; ni < 4; ni++) {
                    int nj = ni >> 1, hl = ni & 1;
                    mma_fp16(acc[mi][ni], af[mi], bfr[nj][hl], bfr[nj][2 + hl]);
                }
        }
    }

    const int er = (lane >> 2);
    const int ec = (lane & 3) * 2;
#pragma unroll
    for (int mi = 0; mi < 4; mi++) {
        float rsum[2] = {0.f, 0.f};
#pragma unroll
        for (int ni = 0; ni < 4; ni++) {
            int row = m0 + wm * 64 + mi * 16 + er;
            int col = n0 + wn * 32 + ni * 8 + ec;
#pragma unroll
            for (int h = 0; h < 2; h++) {
                float v0 = acc[mi][ni][2 * h + 0];
                float v1 = acc[mi][ni][2 * h + 1];
                size_t off = (size_t)(row + 8 * h) * N + col;
                if (MODE == 1) {
                    *reinterpret_cast<__half2*>(ChU + off) = __floats2half2_rn(v0, v1);
                } else if (MODE == 2) {
                    float e0 = exp2f(fmaf(v0, EXP_C1, EXP_C2));
                    float e1 = exp2f(fmaf(v1, EXP_C1, EXP_C2));
                    *reinterpret_cast<__half2*>(ChU + off) = __floats2half2_rn(e0, e1);
                    rsum[h] += e0 + e1;
                } else {   // MODE 4
                    *reinterpret_cast<float2*>(CfU + off) = make_float2(v0, v1);
                }
            }
        }
        if (MODE == 2) {
#pragma unroll
            for (int h = 0; h < 2; h++) {
                float v = rsum[h];
                v += __shfl_xor_sync(0xFFFFFFFFu, v, 1);
                v += __shfl_xor_sync(0xFFFFFFFFu, v, 2);
                if ((lane & 3) == 0)
                    atomicAdd(&rowsum[m0 + wm * 64 + mi * 16 + er + 8 * h], v);
            }
        }
    }
}

// ---------------------------------------------------------------------------
// Fused conversion kernel: img/txt/WQ/WK fp32->fp16 + rowsum zeroing
// ---------------------------------------------------------------------------
constexpr int CN_IMG = N_IMG * DIM / 4;      // float4 counts
constexpr int CN_TXT = N_TXT * DIM / 4;
constexpr int CN_W   = HDIM * DIM / 4;
constexpr int CN_RS  = N_IMG / 4;
constexpr int CN_TOT = CN_IMG + CN_TXT + 2 * CN_W + CN_RS;

__global__ void __launch_bounds__(256)
conv_all_k(const float4* __restrict__ img, const float4* __restrict__ txt,
           const float4* __restrict__ wq, const float4* __restrict__ wk,
           __half* __restrict__ img16, __half* __restrict__ txt16,
           __half* __restrict__ wq16, __half* __restrict__ wk16,
           float4* __restrict__ rowsum)
{
    int i = blockIdx.x * blockDim.x + threadIdx.x;
    const float4* src;
    __half* dst;
    int j = i;
    if (j < CN_IMG)                { src = img; dst = img16; }
    else if ((j -= CN_IMG) < CN_TXT) { src = txt; dst = txt16; }
    else if ((j -= CN_TXT) < CN_W)   { src = wq;  dst = wq16; }
    else if ((j -= CN_W) < CN_W)     { src = wk;  dst = wk16; }
    else {
        j -= CN_W;
        if (j < CN_RS) rowsum[j] = make_float4(0.f, 0.f, 0.f, 0.f);
        return;
    }
    float4 v = src[j];
    __half2* p = reinterpret_cast<__half2*>(dst + (size_t)j * 4);
    p[0] = __floats2half2_rn(v.x, v.y);
    p[1] = __floats2half2_rn(v.z, v.w);
}

// ---------------------------------------------------------------------------
// PV fixup: out = (s0 + s1) / rowsum[row]    (DIM = 1024 -> 256 float4/row)
// ---------------------------------------------------------------------------
__global__ void __launch_bounds__(256)
pv_fix_k(const float4* __restrict__ s0, const float4* __restrict__ s1,
         const float* __restrict__ rowsum, float4* __restrict__ out)
{
    int i = blockIdx.x * blockDim.x + threadIdx.x;   // over N_IMG*DIM/4
    int row = i >> 8;
    float rinv = 1.0f / rowsum[row];
    float4 a = s0[i], b = s1[i];
    out[i] = make_float4((a.x + b.x) * rinv, (a.y + b.y) * rinv,
                         (a.z + b.z) * rinv, (a.w + b.w) * rinv);
}

// ---------------------------------------------------------------------------
// fp32 -> (hi, lo) bf16 split (V path)
// ---------------------------------------------------------------------------
__global__ void __launch_bounds__(256)
split_k(const float4* __restrict__ x, bf16* __restrict__ hi, bf16* __restrict__ lo, int n4)
{
    int i = blockIdx.x * blockDim.x + threadIdx.x;
    if (i >= n4) return;
    float4 v = x[i];
    float f[4] = {v.x, v.y, v.z, v.w};
    bf16 h[4], l[4];
#pragma unroll
    for (int j = 0; j < 4; j++) {
        h[j] = __float2bfloat16(f[j]);
        l[j] = __float2bfloat16(f[j] - __bfloat162float(h[j]));
    }
    __nv_bfloat162* ph = reinterpret_cast<__nv_bfloat162*>(hi + (size_t)i * 4);
    __nv_bfloat162* pl = reinterpret_cast<__nv_bfloat162*>(lo + (size_t)i * 4);
    ph[0] = __nv_bfloat162(h[0], h[1]); ph[1] = __nv_bfloat162(h[2], h[3]);
    pl[0] = __nv_bfloat162(l[0], l[1]); pl[1] = __nv_bfloat162(l[2], l[3]);
}

// ---------------------------------------------------------------------------
extern "C" void kernel_launch(void* const* d_in, const int* in_sizes, int n_in,
                              void* d_out, int out_size)
{
    const float* img = (const float*)d_in[0];   // [N_IMG, DIM]
    const float* txt = (const float*)d_in[1];   // [N_TXT, DIM]
    const float* WQ  = (const float*)d_in[2];   // [HDIM, DIM]
    const float* WK  = (const float*)d_in[3];   // [HDIM, DIM]
    const float* WV  = (const float*)d_in[4];   // [DIM, DIM]
    float* out = (float*)d_out;                 // [N_IMG, DIM]

    static bool init_done = false;
    static cudaStream_t sv = nullptr;
    static cudaEvent_t ev_fork = nullptr, ev_join = nullptr;
    if (!init_done) {
        cudaFuncSetAttribute(proj_gemm, cudaFuncAttributeMaxDynamicSharedMemorySize, GEMM_SMEM);
        cudaFuncSetAttribute(hgemm<1>,  cudaFuncAttributeMaxDynamicSharedMemorySize, H_SMEM);
        cudaFuncSetAttribute(hgemm<2>,  cudaFuncAttributeMaxDynamicSharedMemorySize, H_SMEM);
        cudaFuncSetAttribute(hgemm<4>,  cudaFuncAttributeMaxDynamicSharedMemorySize, H_SMEM);
        cudaStreamCreateWithFlags(&sv, cudaStreamNonBlocking);
        cudaEventCreateWithFlags(&ev_fork, cudaEventDisableTiming);
        cudaEventCreateWithFlags(&ev_join, cudaEventDisableTiming);
        init_done = true;
    }

    __half *img16, *txt16, *wq16, *wk16, *q16, *k16, *vt16, *p16;
    bf16 *txth, *txtl, *wvh, *wvl;
    float *rowsum, *pvs;
    cudaGetSymbolAddress((void**)&img16, g_img16);
    cudaGetSymbolAddress((void**)&txt16, g_txt16);
    cudaGetSymbolAddress((void**)&wq16, g_wq16);
    cudaGetSymbolAddress((void**)&wk16, g_wk16);
    cudaGetSymbolAddress((void**)&txth, g_txth); cudaGetSymbolAddress((void**)&txtl, g_txtl);
    cudaGetSymbolAddress((void**)&wvh, g_wvh);   cudaGetSymbolAddress((void**)&wvl, g_wvl);
    cudaGetSymbolAddress((void**)&q16, g_q16);
    cudaGetSymbolAddress((void**)&k16, g_k16);
    cudaGetSymbolAddress((void**)&vt16, g_vt16);
    cudaGetSymbolAddress((void**)&p16, g_p16);
    cudaGetSymbolAddress((void**)&rowsum, g_rowsum);
    cudaGetSymbolAddress((void**)&pvs, g_pvs);

    auto split = [&](const float* x, bf16* h, bf16* l, size_t n, cudaStream_t st) {
        int n4 = (int)(n / 4);
        split_k<<<(n4 + 255) / 256, 256, 0, st>>>((const float4*)x, h, l, n4);
    };

    // ---- fork: V-projection chain on side stream (independent until PV) ----
    cudaEventRecord(ev_fork, 0);
    cudaStreamWaitEvent(sv, ev_fork, 0);
    split(txt, txth, txtl, (size_t)N_TXT * DIM, sv);
    split(WV,  wvh,  wvl,  (size_t)DIM * DIM,  sv);
    proj_gemm<<<dim3(N_TXT / 128, DIM / 128), 256, GEMM_SMEM, sv>>>(
        wvh, wvl, txth, txtl, vt16, DIM, N_TXT, DIM);
    cudaEventRecord(ev_join, sv);

    // ---- main stream ----
    // fused convs + rowsum zero
    conv_all_k<<<(CN_TOT + 255) / 256, 256>>>(
        (const float4*)img, (const float4*)txt, (const float4*)WQ, (const float4*)WK,
        img16, txt16, wq16, wk16, (float4*)rowsum);

    // merged Q+K projections: z=0 -> Q = img@WQ^T, z=1 -> K = txt@WK^T
    hgemm<1><<<dim3(HDIM / 128, N_IMG / 128, 2), 256, H_SMEM>>>(
        img16, wq16, nullptr, q16, nullptr,
        txt16, wk16, k16,
        N_IMG, HDIM, DIM, DIM, DIM);

    // P~ = exp(Q@K^T/32 - 8) -> fp16, rowsum via atomics
    hgemm<2><<<dim3(N_TXT / 128, N_IMG / 128), 256, H_SMEM>>>(
        q16, k16, nullptr, p16, rowsum,
        nullptr, nullptr, nullptr,
        N_IMG, N_TXT, HDIM, HDIM, HDIM);

    // ---- join: PV needs vt16 ----
    cudaStreamWaitEvent(0, ev_join, 0);

    // split-K PV: z in {0,1} does K-half into disjoint partial buffers
    hgemm<4><<<dim3(DIM / 128, N_IMG / 128, 2), 256, H_SMEM>>>(
        p16, vt16, pvs, nullptr, nullptr,
        nullptr, nullptr, nullptr,
        N_IMG, DIM, N_TXT / 2, N_TXT, N_TXT);

    // fixup: out = (s0 + s1) / rowsum
    pv_fix_k<<<(N_IMG * DIM / 4) / 256, 256>>>(
        (const float4*)pvs, (const float4*)(pvs + (size_t)N_IMG * DIM),
        rowsum, (float4*)out);
}

// round 9
// speedup vs baseline: 1.2546x; 1.2546x over previous
#include <cuda_runtime.h>
#include <cuda_bf16.h>
#include <cuda_fp16.h>
#include <cstdint>

#define N_IMG 8192
#define N_TXT 8192
#define DIM   1024
#define HDIM  1024

typedef __nv_bfloat16 bf16;

// ---------------------------------------------------------------------------
// Device scratch (no allocations allowed)
// ---------------------------------------------------------------------------
__device__ __align__(1024) __half g_img16[(size_t)N_IMG * DIM];
__device__ __align__(1024) __half g_txt16[(size_t)N_TXT * DIM];
__device__ __align__(1024) __half g_wq16 [(size_t)HDIM * DIM];
__device__ __align__(1024) __half g_wk16 [(size_t)HDIM * DIM];
__device__ __align__(1024) bf16 g_txth[(size_t)N_TXT * DIM], g_txtl[(size_t)N_TXT * DIM];
__device__ __align__(1024) bf16 g_wvh [(size_t)DIM * DIM],   g_wvl [(size_t)DIM * DIM];
__device__ __align__(1024) __half g_q16 [(size_t)N_IMG * HDIM];
__device__ __align__(1024) __half g_k16 [(size_t)N_TXT * HDIM];
__device__ __align__(1024) __half g_vt16[(size_t)DIM * N_TXT];
__device__ __align__(1024) __half g_p16 [(size_t)N_IMG * N_TXT];   // 128 MB
__device__ __align__(1024) float  g_rowsum[N_IMG];

// exp constants: exp(s*0.03125 - 8) = exp2(acc*c1 + c2)
#define EXP_C1 0.04508422f      // 0.03125 * log2(e)
#define EXP_C2 -11.54156036f    // -8 * log2(e)

// ---------------------------------------------------------------------------
// Portable PTX helpers
// ---------------------------------------------------------------------------
__device__ __forceinline__ uint32_t smem_to_u32(const void* p) {
    uint32_t a;
    asm("{ .reg .u64 t; cvta.to.shared.u64 t, %1; cvt.u32.u64 %0, t; }" : "=r"(a) : "l"(p));
    return a;
}
__device__ __forceinline__ void ldmatrix_x4(uint32_t* r, uint32_t addr) {
    asm volatile("ldmatrix.sync.aligned.m8n8.x4.shared.b16 {%0,%1,%2,%3}, [%4];"
        : "=r"(r[0]), "=r"(r[1]), "=r"(r[2]), "=r"(r[3]) : "r"(addr));
}
__device__ __forceinline__ void mma_bf16(float* c, const uint32_t* a, uint32_t b0, uint32_t b1) {
    asm volatile("mma.sync.aligned.m16n8k16.row.col.f32.bf16.bf16.f32 "
        "{%0,%1,%2,%3}, {%4,%5,%6,%7}, {%8,%9}, {%0,%1,%2,%3};"
        : "+f"(c[0]), "+f"(c[1]), "+f"(c[2]), "+f"(c[3])
        : "r"(a[0]), "r"(a[1]), "r"(a[2]), "r"(a[3]), "r"(b0), "r"(b1));
}
__device__ __forceinline__ void mma_fp16(float* c, const uint32_t* a, uint32_t b0, uint32_t b1) {
    asm volatile("mma.sync.aligned.m16n8k16.row.col.f32.f16.f16.f32 "
        "{%0,%1,%2,%3}, {%4,%5,%6,%7}, {%8,%9}, {%0,%1,%2,%3};"
        : "+f"(c[0]), "+f"(c[1]), "+f"(c[2]), "+f"(c[3])
        : "r"(a[0]), "r"(a[1]), "r"(a[2]), "r"(a[3]), "r"(b0), "r"(b1));
}
#define CP_ASYNC16(dst, src) \
    asm volatile("cp.async.cg.shared.global [%0], [%1], 16;" :: "r"(dst), "l"(src) : "memory")
#define CP_COMMIT() asm volatile("cp.async.commit_group;" ::: "memory")
#define CP_WAIT1()  asm volatile("cp.async.wait_group 1;" ::: "memory")

// ===========================================================================
// Kernel 1: 3-term compensated bf16 GEMM — V projection (accuracy path)
// ===========================================================================
constexpr int TILE_B = 8192;
constexpr int OFF_AH = 0, OFF_AL = TILE_B, OFF_BH = 2 * TILE_B, OFF_BL = 3 * TILE_B;
constexpr int STG = 4 * TILE_B;
constexpr int NSTAGE = 3;
constexpr int GEMM_SMEM = NSTAGE * STG;      // 96 KB

__device__ __forceinline__ void load_tile32(uint32_t dst, const bf16* __restrict__ src,
                                            int ldK, int tid) {
#pragma unroll
    for (int i = 0; i < 2; i++) {
        int idx = tid + i * 256;
        int r = idx >> 2, c = idx & 3;
        int sc = c ^ ((r >> 1) & 3);
        CP_ASYNC16(dst + r * 64 + (sc << 4), src + (size_t)r * ldK + c * 8);
    }
}

__global__ void __launch_bounds__(256, 1)
proj_gemm(const bf16* __restrict__ Ahi, const bf16* __restrict__ Alo,
          const bf16* __restrict__ Bhi, const bf16* __restrict__ Blo,
          __half* __restrict__ C, int M, int N, int K)
{
    extern __shared__ __align__(1024) char smem[];
    const uint32_t sb = smem_to_u32(smem);
    const int tid  = threadIdx.x;
    const int lane = tid & 31;
    const int wid  = tid >> 5;
    const int wm   = wid & 1;
    const int wn   = wid >> 1;
    const int m0   = blockIdx.y * 128, n0 = blockIdx.x * 128;

    const bf16* Ah = Ahi + (size_t)m0 * K;
    const bf16* Al = Alo + (size_t)m0 * K;
    const bf16* Bh = Bhi + (size_t)n0 * K;
    const bf16* Bl = Blo + (size_t)n0 * K;

    float acc[4][4][4];
#pragma unroll
    for (int i = 0; i < 4; i++)
#pragma unroll
        for (int j = 0; j < 4; j++)
#pragma unroll
            for (int t = 0; t < 4; t++) acc[i][j][t] = 0.f;

    const int NK = K >> 5;

#pragma unroll
    for (int i = 0; i < NSTAGE - 1; i++) {
        if (i < NK) {
            uint32_t st = sb + i * STG;
            int ko = i * 32;
            load_tile32(st + OFF_AH, Ah + ko, K, tid);
            load_tile32(st + OFF_AL, Al + ko, K, tid);
            load_tile32(st + OFF_BH, Bh + ko, K, tid);
            load_tile32(st + OFF_BL, Bl + ko, K, tid);
        }
        CP_COMMIT();
    }

    const int lr = lane & 15;
    const int lc = lane >> 4;

    for (int k = 0; k < NK; k++) {
        CP_WAIT1();
        __syncthreads();

        int kn = k + NSTAGE - 1;
        if (kn < NK) {
            uint32_t st = sb + (kn % NSTAGE) * STG;
            int ko = kn * 32;
            load_tile32(st + OFF_AH, Ah + ko, K, tid);
            load_tile32(st + OFF_AL, Al + ko, K, tid);
            load_tile32(st + OFF_BH, Bh + ko, K, tid);
            load_tile32(st + OFF_BL, Bl + ko, K, tid);
        }
        CP_COMMIT();

        const uint32_t s = sb + (k % NSTAGE) * STG;
#pragma unroll
        for (int ks = 0; ks < 2; ks++) {
            uint32_t ah[4][4], al[4][4], bh[2][4], bl[2][4];
#pragma unroll
            for (int mi = 0; mi < 4; mi++) {
                int r = wm * 64 + mi * 16 + lr;
                int c = ks * 2 + lc;
                int sc = c ^ ((r >> 1) & 3);
                uint32_t a = s + r * 64 + (sc << 4);
                ldmatrix_x4(ah[mi], a + OFF_AH);
                ldmatrix_x4(al[mi], a + OFF_AL);
            }
#pragma unroll
            for (int nj = 0; nj < 2; nj++) {
                int r = wn * 32 + nj * 16 + lr;
                int c = ks * 2 + lc;
                int sc = c ^ ((r >> 1) & 3);
                uint32_t a = s + r * 64 + (sc << 4);
                ldmatrix_x4(bh[nj], a + OFF_BH);
                ldmatrix_x4(bl[nj], a + OFF_BL);
            }
#pragma unroll
            for (int mi = 0; mi < 4; mi++)
#pragma unroll
                for (int ni = 0; ni < 4; ni++) {
                    int nj = ni >> 1, hl = ni & 1;
                    mma_bf16(acc[mi][ni], ah[mi], bh[nj][hl], bh[nj][2 + hl]);
                    mma_bf16(acc[mi][ni], ah[mi], bl[nj][hl], bl[nj][2 + hl]);
                    mma_bf16(acc[mi][ni], al[mi], bh[nj][hl], bh[nj][2 + hl]);
                }
        }
    }

    const int er = (lane >> 2);
    const int ec = (lane & 3) * 2;
#pragma unroll
    for (int mi = 0; mi < 4; mi++)
#pragma unroll
        for (int ni = 0; ni < 4; ni++) {
            int row = m0 + wm * 64 + mi * 16 + er;
            int col = n0 + wn * 32 + ni * 8 + ec;
#pragma unroll
            for (int h = 0; h < 2; h++) {
                float v0 = acc[mi][ni][2 * h + 0];
                float v1 = acc[mi][ni][2 * h + 1];
                size_t off = (size_t)(row + 8 * h) * N + col;
                *reinterpret_cast<__half2*>(C + off) = __floats2half2_rn(v0, v1);
            }
        }
}

// ===========================================================================
// Kernel 2: single-term fp16 GEMM, epilogue modes (R7 structure):
//   MODE 1: C fp16; dual operand sets via blockIdx.z (merged Q+K projections)
//   MODE 2: C fp16 = exp2(acc*EXP_C1 + EXP_C2) + rowsum atomics  (QK^T)
//   MODE 3: C fp32 = acc / rowsum[row]                           (PV, no split)
// ===========================================================================
constexpr int H_TILE = 16384;
constexpr int H_OFF_A = 0, H_OFF_B = H_TILE;
constexpr int H_STG = 2 * H_TILE;
constexpr int H_NSTAGE = 3;
constexpr int H_SMEM = H_NSTAGE * H_STG;     // 96 KB

__device__ __forceinline__ void load_tile64h(uint32_t dst, const __half* __restrict__ src,
                                             int ldK, int tid) {
#pragma unroll
    for (int i = 0; i < 4; i++) {
        int idx = tid + i * 256;
        int r = idx >> 3, c = idx & 7;
        int sc = c ^ (r & 7);
        CP_ASYNC16(dst + r * 128 + (sc << 4), src + (size_t)r * ldK + c * 8);
    }
}

template <int MODE>
__global__ void __launch_bounds__(256, 1)
hgemm(const __half* __restrict__ A, const __half* __restrict__ B,
      float* __restrict__ Cf, __half* __restrict__ Ch,
      float* __restrict__ rowsum,
      const __half* __restrict__ A2, const __half* __restrict__ B2,
      __half* __restrict__ Ch2,
      int M, int N, int K)
{
    extern __shared__ __align__(1024) char smem[];
    const uint32_t sb = smem_to_u32(smem);
    const int tid  = threadIdx.x;
    const int lane = tid & 31;
    const int wid  = tid >> 5;
    const int wm   = wid & 1;
    const int wn   = wid >> 1;
    const int m0   = blockIdx.y * 128, n0 = blockIdx.x * 128;

    const __half* Abase = A;
    const __half* Bbase = B;
    __half* ChU = Ch;
    if (MODE == 1 && blockIdx.z == 1) { Abase = A2; Bbase = B2; ChU = Ch2; }

    const __half* Ar = Abase + (size_t)m0 * K;
    const __half* Br = Bbase + (size_t)n0 * K;

    float acc[4][4][4];
#pragma unroll
    for (int i = 0; i < 4; i++)
#pragma unroll
        for (int j = 0; j < 4; j++)
#pragma unroll
            for (int t = 0; t < 4; t++) acc[i][j][t] = 0.f;

    const int NK = K >> 6;

#pragma unroll
    for (int i = 0; i < H_NSTAGE - 1; i++) {
        if (i < NK) {
            uint32_t st = sb + i * H_STG;
            int ko = i * 64;
            load_tile64h(st + H_OFF_A, Ar + ko, K, tid);
            load_tile64h(st + H_OFF_B, Br + ko, K, tid);
        }
        CP_COMMIT();
    }

    const int lr = lane & 15;
    const int lc = lane >> 4;

    for (int k = 0; k < NK; k++) {
        CP_WAIT1();
        __syncthreads();

        int kn = k + H_NSTAGE - 1;
        if (kn < NK) {
            uint32_t st = sb + (kn % H_NSTAGE) * H_STG;
            int ko = kn * 64;
            load_tile64h(st + H_OFF_A, Ar + ko, K, tid);
            load_tile64h(st + H_OFF_B, Br + ko, K, tid);
        }
        CP_COMMIT();

        const uint32_t s = sb + (k % H_NSTAGE) * H_STG;
#pragma unroll
        for (int ks = 0; ks < 4; ks++) {
            uint32_t af[4][4], bfr[2][4];
#pragma unroll
            for (int mi = 0; mi < 4; mi++) {
                int r = wm * 64 + mi * 16 + lr;
                int c = ks * 2 + lc;
                int sc = c ^ (r & 7);
                ldmatrix_x4(af[mi], s + H_OFF_A + r * 128 + (sc << 4));
            }
#pragma unroll
            for (int nj = 0; nj < 2; nj++) {
                int r = wn * 32 + nj * 16 + lr;
                int c = ks * 2 + lc;
                int sc = c ^ (r & 7);
                ldmatrix_x4(bfr[nj], s + H_OFF_B + r * 128 + (sc << 4));
            }
#pragma unroll
            for (int mi = 0; mi < 4; mi++)
#pragma unroll
                for (int ni = 0; ni < 4; ni++) {
                    int nj = ni >> 1, hl = ni & 1;
                    mma_fp16(acc[mi][ni], af[mi], bfr[nj][hl], bfr[nj][2 + hl]);
                }
        }
    }

    const int er = (lane >> 2);
    const int ec = (lane & 3) * 2;
#pragma unroll
    for (int mi = 0; mi < 4; mi++) {
        float rsum[2] = {0.f, 0.f};
        float rinv[2];
        if (MODE == 3) {
            rinv[0] = 1.0f / rowsum[m0 + wm * 64 + mi * 16 + er];
            rinv[1] = 1.0f / rowsum[m0 + wm * 64 + mi * 16 + er + 8];
        }
#pragma unroll
        for (int ni = 0; ni < 4; ni++) {
            int row = m0 + wm * 64 + mi * 16 + er;
            int col = n0 + wn * 32 + ni * 8 + ec;
#pragma unroll
            for (int h = 0; h < 2; h++) {
                float v0 = acc[mi][ni][2 * h + 0];
                float v1 = acc[mi][ni][2 * h + 1];
                size_t off = (size_t)(row + 8 * h) * N + col;
                if (MODE == 1) {
                    *reinterpret_cast<__half2*>(ChU + off) = __floats2half2_rn(v0, v1);
                } else if (MODE == 2) {
                    float e0 = exp2f(fmaf(v0, EXP_C1, EXP_C2));
                    float e1 = exp2f(fmaf(v1, EXP_C1, EXP_C2));
                    *reinterpret_cast<__half2*>(ChU + off) = __floats2half2_rn(e0, e1);
                    rsum[h] += e0 + e1;
                } else {   // MODE 3
                    *reinterpret_cast<float2*>(Cf + off) =
                        make_float2(v0 * rinv[h], v1 * rinv[h]);
                }
            }
        }
        if (MODE == 2) {
#pragma unroll
            for (int h = 0; h < 2; h++) {
                float v = rsum[h];
                v += __shfl_xor_sync(0xFFFFFFFFu, v, 1);
                v += __shfl_xor_sync(0xFFFFFFFFu, v, 2);
                if ((lane & 3) == 0)
                    atomicAdd(&rowsum[m0 + wm * 64 + mi * 16 + er + 8 * h], v);
            }
        }
    }
}

// ---------------------------------------------------------------------------
// Fused conversion kernel: img/txt/WQ/WK fp32->fp16 + rowsum zeroing
// ---------------------------------------------------------------------------
constexpr int CN_IMG = N_IMG * DIM / 4;      // float4 counts
constexpr int CN_TXT = N_TXT * DIM / 4;
constexpr int CN_W   = HDIM * DIM / 4;
constexpr int CN_RS  = N_IMG / 4;
constexpr int CN_TOT = CN_IMG + CN_TXT + 2 * CN_W + CN_RS;

__global__ void __launch_bounds__(256)
conv_all_k(const float4* __restrict__ img, const float4* __restrict__ txt,
           const float4* __restrict__ wq, const float4* __restrict__ wk,
           __half* __restrict__ img16, __half* __restrict__ txt16,
           __half* __restrict__ wq16, __half* __restrict__ wk16,
           float4* __restrict__ rowsum)
{
    int i = blockIdx.x * blockDim.x + threadIdx.x;
    const float4* src;
    __half* dst;
    int j = i;
    if (j < CN_IMG)                  { src = img; dst = img16; }
    else if ((j -= CN_IMG) < CN_TXT) { src = txt; dst = txt16; }
    else if ((j -= CN_TXT) < CN_W)   { src = wq;  dst = wq16; }
    else if ((j -= CN_W) < CN_W)     { src = wk;  dst = wk16; }
    else {
        j -= CN_W;
        if (j < CN_RS) rowsum[j] = make_float4(0.f, 0.f, 0.f, 0.f);
        return;
    }
    float4 v = src[j];
    __half2* p = reinterpret_cast<__half2*>(dst + (size_t)j * 4);
    p[0] = __floats2half2_rn(v.x, v.y);
    p[1] = __floats2half2_rn(v.z, v.w);
}

// ---------------------------------------------------------------------------
// fp32 -> (hi, lo) bf16 split (V path)
// ---------------------------------------------------------------------------
__global__ void __launch_bounds__(256)
split_k(const float4* __restrict__ x, bf16* __restrict__ hi, bf16* __restrict__ lo, int n4)
{
    int i = blockIdx.x * blockDim.x + threadIdx.x;
    if (i >= n4) return;
    float4 v = x[i];
    float f[4] = {v.x, v.y, v.z, v.w};
    bf16 h[4], l[4];
#pragma unroll
    for (int j = 0; j < 4; j++) {
        h[j] = __float2bfloat16(f[j]);
        l[j] = __float2bfloat16(f[j] - __bfloat162float(h[j]));
    }
    __nv_bfloat162* ph = reinterpret_cast<__nv_bfloat162*>(hi + (size_t)i * 4);
    __nv_bfloat162* pl = reinterpret_cast<__nv_bfloat162*>(lo + (size_t)i * 4);
    ph[0] = __nv_bfloat162(h[0], h[1]); ph[1] = __nv_bfloat162(h[2], h[3]);
    pl[0] = __nv_bfloat162(l[0], l[1]); pl[1] = __nv_bfloat162(l[2], l[3]);
}

// ---------------------------------------------------------------------------
extern "C" void kernel_launch(void* const* d_in, const int* in_sizes, int n_in,
                              void* d_out, int out_size)
{
    const float* img = (const float*)d_in[0];   // [N_IMG, DIM]
    const float* txt = (const float*)d_in[1];   // [N_TXT, DIM]
    const float* WQ  = (const float*)d_in[2];   // [HDIM, DIM]
    const float* WK  = (const float*)d_in[3];   // [HDIM, DIM]
    const float* WV  = (const float*)d_in[4];   // [DIM, DIM]
    float* out = (float*)d_out;                 // [N_IMG, DIM]

    static bool init_done = false;
    static cudaStream_t sv = nullptr;
    static cudaEvent_t ev_fork = nullptr, ev_join = nullptr;
    if (!init_done) {
        cudaFuncSetAttribute(proj_gemm, cudaFuncAttributeMaxDynamicSharedMemorySize, GEMM_SMEM);
        cudaFuncSetAttribute(hgemm<1>,  cudaFuncAttributeMaxDynamicSharedMemorySize, H_SMEM);
        cudaFuncSetAttribute(hgemm<2>,  cudaFuncAttributeMaxDynamicSharedMemorySize, H_SMEM);
        cudaFuncSetAttribute(hgemm<3>,  cudaFuncAttributeMaxDynamicSharedMemorySize, H_SMEM);
        cudaStreamCreateWithFlags(&sv, cudaStreamNonBlocking);
        cudaEventCreateWithFlags(&ev_fork, cudaEventDisableTiming);
        cudaEventCreateWithFlags(&ev_join, cudaEventDisableTiming);
        init_done = true;
    }

    __half *img16, *txt16, *wq16, *wk16, *q16, *k16, *vt16, *p16;
    bf16 *txth, *txtl, *wvh, *wvl;
    float *rowsum;
    cudaGetSymbolAddress((void**)&img16, g_img16);
    cudaGetSymbolAddress((void**)&txt16, g_txt16);
    cudaGetSymbolAddress((void**)&wq16, g_wq16);
    cudaGetSymbolAddress((void**)&wk16, g_wk16);
    cudaGetSymbolAddress((void**)&txth, g_txth); cudaGetSymbolAddress((void**)&txtl, g_txtl);
    cudaGetSymbolAddress((void**)&wvh, g_wvh);   cudaGetSymbolAddress((void**)&wvl, g_wvl);
    cudaGetSymbolAddress((void**)&q16, g_q16);
    cudaGetSymbolAddress((void**)&k16, g_k16);
    cudaGetSymbolAddress((void**)&vt16, g_vt16);
    cudaGetSymbolAddress((void**)&p16, g_p16);
    cudaGetSymbolAddress((void**)&rowsum, g_rowsum);

    auto split = [&](const float* x, bf16* h, bf16* l, size_t n, cudaStream_t st) {
        int n4 = (int)(n / 4);
        split_k<<<(n4 + 255) / 256, 256, 0, st>>>((const float4*)x, h, l, n4);
    };

    // ---- fork: V-projection chain on side stream (independent until PV) ----
    cudaEventRecord(ev_fork, 0);
    cudaStreamWaitEvent(sv, ev_fork, 0);
    split(txt, txth, txtl, (size_t)N_TXT * DIM, sv);
    split(WV,  wvh,  wvl,  (size_t)DIM * DIM,  sv);
    proj_gemm<<<dim3(N_TXT / 128, DIM / 128), 256, GEMM_SMEM, sv>>>(
        wvh, wvl, txth, txtl, vt16, DIM, N_TXT, DIM);
    cudaEventRecord(ev_join, sv);

    // ---- main stream ----
    // fused convs + rowsum zero (one launch)
    conv_all_k<<<(CN_TOT + 255) / 256, 256>>>(
        (const float4*)img, (const float4*)txt, (const float4*)WQ, (const float4*)WK,
        img16, txt16, wq16, wk16, (float4*)rowsum);

    // merged Q+K projections: z=0 -> Q = img@WQ^T, z=1 -> K = txt@WK^T
    hgemm<1><<<dim3(HDIM / 128, N_IMG / 128, 2), 256, H_SMEM>>>(
        img16, wq16, nullptr, q16, nullptr,
        txt16, wk16, k16,
        N_IMG, HDIM, DIM);

    // P~ = exp(Q@K^T/32 - 8) -> fp16, rowsum via atomics
    hgemm<2><<<dim3(N_TXT / 128, N_IMG / 128), 256, H_SMEM>>>(
        q16, k16, nullptr, p16, rowsum,
        nullptr, nullptr, nullptr,
        N_IMG, N_TXT, HDIM);

    // ---- join: PV needs vt16 ----
    cudaStreamWaitEvent(0, ev_join, 0);
    // out = (P~ @ Vt^T) / rowsum[row] -> fp32  (R7 MODE 3, no split-K)
    hgemm<3><<<dim3(DIM / 128, N_IMG / 128), 256, H_SMEM>>>(
        p16, vt16, out, nullptr, rowsum,
        nullptr, nullptr, nullptr,
        N_IMG, DIM, N_TXT);
}

// round 10
// speedup vs baseline: 1.3531x; 1.0785x over previous
#include <cuda_runtime.h>
#include <cuda_fp16.h>
#include <cstdint>

#define N_IMG 8192
#define N_TXT 8192
#define DIM   1024
#define HDIM  1024

// ---------------------------------------------------------------------------
// Device scratch (no allocations allowed)
// ---------------------------------------------------------------------------
__device__ __align__(1024) __half g_img16[(size_t)N_IMG * DIM];
__device__ __align__(1024) __half g_txt16[(size_t)N_TXT * DIM];
__device__ __align__(1024) __half g_wqT16[(size_t)DIM * HDIM];     // Wq^T [D,H]
__device__ __align__(1024) __half g_wkT16[(size_t)DIM * HDIM];     // Wk^T [D,H]
__device__ __align__(1024) __half g_m1t16[(size_t)DIM * DIM];      // (Wq^T Wk)^T
__device__ __align__(1024) __half g_wvh16[(size_t)DIM * DIM];      // fp16 hi of WV
__device__ __align__(1024) __half g_wvl16[(size_t)DIM * DIM];      // fp16 lo of WV
__device__ __align__(1024) __half g_q16 [(size_t)N_IMG * HDIM];    // A2 = img @ M1
__device__ __align__(1024) __half g_vt16[(size_t)DIM * N_TXT];
__device__ __align__(1024) __half g_p16 [(size_t)N_IMG * N_TXT];   // 128 MB
__device__ __align__(1024) float  g_rowsum[N_IMG];

// exp constants: exp(s*0.03125 - 8) = exp2(acc*c1 + c2)
#define EXP_C1 0.04508422f      // 0.03125 * log2(e)
#define EXP_C2 -11.54156036f    // -8 * log2(e)

// ---------------------------------------------------------------------------
// Portable PTX helpers
// ---------------------------------------------------------------------------
__device__ __forceinline__ uint32_t smem_to_u32(const void* p) {
    uint32_t a;
    asm("{ .reg .u64 t; cvta.to.shared.u64 t, %1; cvt.u32.u64 %0, t; }" : "=r"(a) : "l"(p));
    return a;
}
__device__ __forceinline__ void ldmatrix_x4(uint32_t* r, uint32_t addr) {
    asm volatile("ldmatrix.sync.aligned.m8n8.x4.shared.b16 {%0,%1,%2,%3}, [%4];"
        : "=r"(r[0]), "=r"(r[1]), "=r"(r[2]), "=r"(r[3]) : "r"(addr));
}
__device__ __forceinline__ void mma_fp16(float* c, const uint32_t* a, uint32_t b0, uint32_t b1) {
    asm volatile("mma.sync.aligned.m16n8k16.row.col.f32.f16.f16.f32 "
        "{%0,%1,%2,%3}, {%4,%5,%6,%7}, {%8,%9}, {%0,%1,%2,%3};"
        : "+f"(c[0]), "+f"(c[1]), "+f"(c[2]), "+f"(c[3])
        : "r"(a[0]), "r"(a[1]), "r"(a[2]), "r"(a[3]), "r"(b0), "r"(b1));
}
#define CP_ASYNC16(dst, src) \
    asm volatile("cp.async.cg.shared.global [%0], [%1], 16;" :: "r"(dst), "l"(src) : "memory")
#define CP_COMMIT() asm volatile("cp.async.commit_group;" ::: "memory")
#define CP_WAIT1()  asm volatile("cp.async.wait_group 1;" ::: "memory")

// ===========================================================================
// Shared tile loader: 128 rows x 64 fp16 (128 B/row), swizzle c ^= r&7
// ===========================================================================
__device__ __forceinline__ void load_tile64h(uint32_t dst, const __half* __restrict__ src,
                                             int ldK, int tid) {
#pragma unroll
    for (int i = 0; i < 4; i++) {
        int idx = tid + i * 256;
        int r = idx >> 3, c = idx & 7;
        int sc = c ^ (r & 7);
        CP_ASYNC16(dst + r * 128 + (sc << 4), src + (size_t)r * ldK + c * 8);
    }
}

// ===========================================================================
// Kernel: single-term fp16 GEMM (C = A[M,K] @ B[N,K]^T), epilogue modes:
//   MODE 1: C fp16
//   MODE 2: C fp16 = exp2(acc*EXP_C1 + EXP_C2) + rowsum atomics  (QK^T)
//   MODE 3: C fp32 = acc / rowsum[row]                           (PV)
// ===========================================================================
constexpr int H_TILE = 16384;
constexpr int H_OFF_A = 0, H_OFF_B = H_TILE;
constexpr int H_STG = 2 * H_TILE;
constexpr int H_NSTAGE = 3;
constexpr int H_SMEM = H_NSTAGE * H_STG;     // 96 KB

template <int MODE>
__global__ void __launch_bounds__(256, 1)
hgemm(const __half* __restrict__ A, const __half* __restrict__ B,
      float* __restrict__ Cf, __half* __restrict__ Ch,
      float* __restrict__ rowsum, int M, int N, int K)
{
    extern __shared__ __align__(1024) char smem[];
    const uint32_t sb = smem_to_u32(smem);
    const int tid  = threadIdx.x;
    const int lane = tid & 31;
    const int wid  = tid >> 5;
    const int wm   = wid & 1;
    const int wn   = wid >> 1;
    const int m0   = blockIdx.y * 128, n0 = blockIdx.x * 128;

    const __half* Ar = A + (size_t)m0 * K;
    const __half* Br = B + (size_t)n0 * K;

    float acc[4][4][4];
#pragma unroll
    for (int i = 0; i < 4; i++)
#pragma unroll
        for (int j = 0; j < 4; j++)
#pragma unroll
            for (int t = 0; t < 4; t++) acc[i][j][t] = 0.f;

    const int NK = K >> 6;

#pragma unroll
    for (int i = 0; i < H_NSTAGE - 1; i++) {
        if (i < NK) {
            uint32_t st = sb + i * H_STG;
            int ko = i * 64;
            load_tile64h(st + H_OFF_A, Ar + ko, K, tid);
            load_tile64h(st + H_OFF_B, Br + ko, K, tid);
        }
        CP_COMMIT();
    }

    const int lr = lane & 15;
    const int lc = lane >> 4;

    for (int k = 0; k < NK; k++) {
        CP_WAIT1();
        __syncthreads();

        int kn = k + H_NSTAGE - 1;
        if (kn < NK) {
            uint32_t st = sb + (kn % H_NSTAGE) * H_STG;
            int ko = kn * 64;
            load_tile64h(st + H_OFF_A, Ar + ko, K, tid);
            load_tile64h(st + H_OFF_B, Br + ko, K, tid);
        }
        CP_COMMIT();

        const uint32_t s = sb + (k % H_NSTAGE) * H_STG;
#pragma unroll
        for (int ks = 0; ks < 4; ks++) {
            uint32_t af[4][4], bfr[2][4];
#pragma unroll
            for (int mi = 0; mi < 4; mi++) {
                int r = wm * 64 + mi * 16 + lr;
                int c = ks * 2 + lc;
                int sc = c ^ (r & 7);
                ldmatrix_x4(af[mi], s + H_OFF_A + r * 128 + (sc << 4));
            }
#pragma unroll
            for (int nj = 0; nj < 2; nj++) {
                int r = wn * 32 + nj * 16 + lr;
                int c = ks * 2 + lc;
                int sc = c ^ (r & 7);
                ldmatrix_x4(bfr[nj], s + H_OFF_B + r * 128 + (sc << 4));
            }
#pragma unroll
            for (int mi = 0; mi < 4; mi++)
#pragma unroll
                for (int ni = 0; ni < 4; ni++) {
                    int nj = ni >> 1, hl = ni & 1;
                    mma_fp16(acc[mi][ni], af[mi], bfr[nj][hl], bfr[nj][2 + hl]);
                }
        }
    }

    const int er = (lane >> 2);
    const int ec = (lane & 3) * 2;
#pragma unroll
    for (int mi = 0; mi < 4; mi++) {
        float rsum[2] = {0.f, 0.f};
        float rinv[2];
        if (MODE == 3) {
            rinv[0] = 1.0f / rowsum[m0 + wm * 64 + mi * 16 + er];
            rinv[1] = 1.0f / rowsum[m0 + wm * 64 + mi * 16 + er + 8];
        }
#pragma unroll
        for (int ni = 0; ni < 4; ni++) {
            int row = m0 + wm * 64 + mi * 16 + er;
            int col = n0 + wn * 32 + ni * 8 + ec;
#pragma unroll
            for (int h = 0; h < 2; h++) {
                float v0 = acc[mi][ni][2 * h + 0];
                float v1 = acc[mi][ni][2 * h + 1];
                size_t off = (size_t)(row + 8 * h) * N + col;
                if (MODE == 1) {
                    *reinterpret_cast<__half2*>(Ch + off) = __floats2half2_rn(v0, v1);
                } else if (MODE == 2) {
                    float e0 = exp2f(fmaf(v0, EXP_C1, EXP_C2));
                    float e1 = exp2f(fmaf(v1, EXP_C1, EXP_C2));
                    *reinterpret_cast<__half2*>(Ch + off) = __floats2half2_rn(e0, e1);
                    rsum[h] += e0 + e1;
                } else {   // MODE 3
                    *reinterpret_cast<float2*>(Cf + off) =
                        make_float2(v0 * rinv[h], v1 * rinv[h]);
                }
            }
        }
        if (MODE == 2) {
#pragma unroll
            for (int h = 0; h < 2; h++) {
                float v = rsum[h];
                v += __shfl_xor_sync(0xFFFFFFFFu, v, 1);
                v += __shfl_xor_sync(0xFFFFFFFFu, v, 2);
                if ((lane & 3) == 0)
                    atomicAdd(&rowsum[m0 + wm * 64 + mi * 16 + er + 8 * h], v);
            }
        }
    }
}

// ===========================================================================
// Kernel: 2-term fp16 GEMM (V projection): C = (Ahi+Alo)[M,K] @ B[N,K]^T
// ===========================================================================
constexpr int P2_OFF_AH = 0, P2_OFF_AL = 16384, P2_OFF_B = 32768;
constexpr int P2_STG = 3 * 16384;            // 48 KB per stage
constexpr int P2_NSTAGE = 3;
constexpr int P2_SMEM = P2_NSTAGE * P2_STG;  // 144 KB

__global__ void __launch_bounds__(256, 1)
proj2_gemm(const __half* __restrict__ Ahi, const __half* __restrict__ Alo,
           const __half* __restrict__ B, __half* __restrict__ C,
           int M, int N, int K)
{
    extern __shared__ __align__(1024) char smem[];
    const uint32_t sb = smem_to_u32(smem);
    const int tid  = threadIdx.x;
    const int lane = tid & 31;
    const int wid  = tid >> 5;
    const int wm   = wid & 1;
    const int wn   = wid >> 1;
    const int m0   = blockIdx.y * 128, n0 = blockIdx.x * 128;

    const __half* Ah = Ahi + (size_t)m0 * K;
    const __half* Al = Alo + (size_t)m0 * K;
    const __half* Br = B   + (size_t)n0 * K;

    float acc[4][4][4];
#pragma unroll
    for (int i = 0; i < 4; i++)
#pragma unroll
        for (int j = 0; j < 4; j++)
#pragma unroll
            for (int t = 0; t < 4; t++) acc[i][j][t] = 0.f;

    const int NK = K >> 6;

#pragma unroll
    for (int i = 0; i < P2_NSTAGE - 1; i++) {
        if (i < NK) {
            uint32_t st = sb + i * P2_STG;
            int ko = i * 64;
            load_tile64h(st + P2_OFF_AH, Ah + ko, K, tid);
            load_tile64h(st + P2_OFF_AL, Al + ko, K, tid);
            load_tile64h(st + P2_OFF_B,  Br + ko, K, tid);
        }
        CP_COMMIT();
    }

    const int lr = lane & 15;
    const int lc = lane >> 4;

    for (int k = 0; k < NK; k++) {
        CP_WAIT1();
        __syncthreads();

        int kn = k + P2_NSTAGE - 1;
        if (kn < NK) {
            uint32_t st = sb + (kn % P2_NSTAGE) * P2_STG;
            int ko = kn * 64;
            load_tile64h(st + P2_OFF_AH, Ah + ko, K, tid);
            load_tile64h(st + P2_OFF_AL, Al + ko, K, tid);
            load_tile64h(st + P2_OFF_B,  Br + ko, K, tid);
        }
        CP_COMMIT();

        const uint32_t s = sb + (k % P2_NSTAGE) * P2_STG;
#pragma unroll
        for (int ks = 0; ks < 4; ks++) {
            uint32_t ah[4][4], al[4][4], bfr[2][4];
#pragma unroll
            for (int mi = 0; mi < 4; mi++) {
                int r = wm * 64 + mi * 16 + lr;
                int c = ks * 2 + lc;
                int sc = c ^ (r & 7);
                ldmatrix_x4(ah[mi], s + P2_OFF_AH + r * 128 + (sc << 4));
                ldmatrix_x4(al[mi], s + P2_OFF_AL + r * 128 + (sc << 4));
            }
#pragma unroll
            for (int nj = 0; nj < 2; nj++) {
                int r = wn * 32 + nj * 16 + lr;
                int c = ks * 2 + lc;
                int sc = c ^ (r & 7);
                ldmatrix_x4(bfr[nj], s + P2_OFF_B + r * 128 + (sc << 4));
            }
#pragma unroll
            for (int mi = 0; mi < 4; mi++)
#pragma unroll
                for (int ni = 0; ni < 4; ni++) {
                    int nj = ni >> 1, hl = ni & 1;
                    mma_fp16(acc[mi][ni], ah[mi], bfr[nj][hl], bfr[nj][2 + hl]);
                    mma_fp16(acc[mi][ni], al[mi], bfr[nj][hl], bfr[nj][2 + hl]);
                }
        }
    }

    const int er = (lane >> 2);
    const int ec = (lane & 3) * 2;
#pragma unroll
    for (int mi = 0; mi < 4; mi++)
#pragma unroll
        for (int ni = 0; ni < 4; ni++) {
            int row = m0 + wm * 64 + mi * 16 + er;
            int col = n0 + wn * 32 + ni * 8 + ec;
#pragma unroll
            for (int h = 0; h < 2; h++) {
                size_t off = (size_t)(row + 8 * h) * N + col;
                *reinterpret_cast<__half2*>(C + off) =
                    __floats2half2_rn(acc[mi][ni][2 * h], acc[mi][ni][2 * h + 1]);
            }
        }
}

// ---------------------------------------------------------------------------
// img fp32->fp16 + rowsum zeroing (main stream)
// ---------------------------------------------------------------------------
constexpr int CN_IMG = N_IMG * DIM / 4;
constexpr int CN_RS  = N_IMG / 4;
constexpr int CN_MAIN = CN_IMG + CN_RS;

__global__ void __launch_bounds__(256)
conv_img_k(const float4* __restrict__ img, __half* __restrict__ img16,
           float4* __restrict__ rowsum)
{
    int i = blockIdx.x * blockDim.x + threadIdx.x;
    if (i < CN_IMG) {
        float4 v = img[i];
        __half2* p = reinterpret_cast<__half2*>(img16 + (size_t)i * 4);
        p[0] = __floats2half2_rn(v.x, v.y);
        p[1] = __floats2half2_rn(v.z, v.w);
    } else if (i - CN_IMG < CN_RS) {
        rowsum[i - CN_IMG] = make_float4(0.f, 0.f, 0.f, 0.f);
    }
}

// ---------------------------------------------------------------------------
// txt fp32->fp16 (side stream)
// ---------------------------------------------------------------------------
__global__ void __launch_bounds__(256)
conv16_k(const float4* __restrict__ x, __half* __restrict__ y, int n4)
{
    int i = blockIdx.x * blockDim.x + threadIdx.x;
    if (i >= n4) return;
    float4 v = x[i];
    __half2* p = reinterpret_cast<__half2*>(y + (size_t)i * 4);
    p[0] = __floats2half2_rn(v.x, v.y);
    p[1] = __floats2half2_rn(v.z, v.w);
}

// ---------------------------------------------------------------------------
// Wq/Wk fp32 -> fp16 TRANSPOSED (smem tiled); z selects which weight
// ---------------------------------------------------------------------------
__global__ void __launch_bounds__(256)
tconv_k(const float* __restrict__ wq, const float* __restrict__ wk,
        __half* __restrict__ wqT, __half* __restrict__ wkT)
{
    __shared__ float tile[32][33];
    const float* src = blockIdx.z ? wk : wq;
    __half* dst = blockIdx.z ? wkT : wqT;
    int x0 = blockIdx.x * 32;   // column (d) base
    int y0 = blockIdx.y * 32;   // row (h) base
    int tx = threadIdx.x & 31, ty = threadIdx.x >> 5;   // 32x8
#pragma unroll
    for (int i = 0; i < 4; i++)
        tile[ty + i * 8][tx] = src[(size_t)(y0 + ty + i * 8) * DIM + x0 + tx];
    __syncthreads();
#pragma unroll
    for (int i = 0; i < 4; i++)
        dst[(size_t)(x0 + ty + i * 8) * HDIM + y0 + tx] =
            __float2half_rn(tile[tx][ty + i * 8]);
}

// ---------------------------------------------------------------------------
// WV fp32 -> fp16 (hi, lo) split (side stream)
// ---------------------------------------------------------------------------
__global__ void __launch_bounds__(256)
splitv16_k(const float4* __restrict__ x, __half* __restrict__ hi,
           __half* __restrict__ lo, int n4)
{
    int i = blockIdx.x * blockDim.x + threadIdx.x;
    if (i >= n4) return;
    float4 v = x[i];
    float f[4] = {v.x, v.y, v.z, v.w};
    __half h[4], l[4];
#pragma unroll
    for (int j = 0; j < 4; j++) {
        h[j] = __float2half_rn(f[j]);
        l[j] = __float2half_rn(f[j] - __half2float(h[j]));
    }
    __half2* ph = reinterpret_cast<__half2*>(hi + (size_t)i * 4);
    __half2* pl = reinterpret_cast<__half2*>(lo + (size_t)i * 4);
    ph[0] = __half2(h[0], h[1]); ph[1] = __half2(h[2], h[3]);
    pl[0] = __half2(l[0], l[1]); pl[1] = __half2(l[2], l[3]);
}

// ---------------------------------------------------------------------------
extern "C" void kernel_launch(void* const* d_in, const int* in_sizes, int n_in,
                              void* d_out, int out_size)
{
    const float* img = (const float*)d_in[0];   // [N_IMG, DIM]
    const float* txt = (const float*)d_in[1];   // [N_TXT, DIM]
    const float* WQ  = (const float*)d_in[2];   // [HDIM, DIM]
    const float* WK  = (const float*)d_in[3];   // [HDIM, DIM]
    const float* WV  = (const float*)d_in[4];   // [DIM, DIM]
    float* out = (float*)d_out;                 // [N_IMG, DIM]

    static bool init_done = false;
    static cudaStream_t sv = nullptr;
    static cudaEvent_t ev_fork = nullptr, ev_txt = nullptr, ev_join = nullptr;
    if (!init_done) {
        cudaFuncSetAttribute(hgemm<1>, cudaFuncAttributeMaxDynamicSharedMemorySize, H_SMEM);
        cudaFuncSetAttribute(hgemm<2>, cudaFuncAttributeMaxDynamicSharedMemorySize, H_SMEM);
        cudaFuncSetAttribute(hgemm<3>, cudaFuncAttributeMaxDynamicSharedMemorySize, H_SMEM);
        cudaFuncSetAttribute(proj2_gemm, cudaFuncAttributeMaxDynamicSharedMemorySize, P2_SMEM);
        cudaStreamCreateWithFlags(&sv, cudaStreamNonBlocking);
        cudaEventCreateWithFlags(&ev_fork, cudaEventDisableTiming);
        cudaEventCreateWithFlags(&ev_txt,  cudaEventDisableTiming);
        cudaEventCreateWithFlags(&ev_join, cudaEventDisableTiming);
        init_done = true;
    }

    __half *img16, *txt16, *wqT16, *wkT16, *m1t16, *wvh16, *wvl16, *q16, *vt16, *p16;
    float *rowsum;
    cudaGetSymbolAddress((void**)&img16, g_img16);
    cudaGetSymbolAddress((void**)&txt16, g_txt16);
    cudaGetSymbolAddress((void**)&wqT16, g_wqT16);
    cudaGetSymbolAddress((void**)&wkT16, g_wkT16);
    cudaGetSymbolAddress((void**)&m1t16, g_m1t16);
    cudaGetSymbolAddress((void**)&wvh16, g_wvh16);
    cudaGetSymbolAddress((void**)&wvl16, g_wvl16);
    cudaGetSymbolAddress((void**)&q16, g_q16);
    cudaGetSymbolAddress((void**)&vt16, g_vt16);
    cudaGetSymbolAddress((void**)&p16, g_p16);
    cudaGetSymbolAddress((void**)&rowsum, g_rowsum);

    // ---- fork: side stream = txt conv + V chain ----
    cudaEventRecord(ev_fork, 0);
    cudaStreamWaitEvent(sv, ev_fork, 0);
    conv16_k<<<(N_TXT * DIM / 4 + 255) / 256, 256, 0, sv>>>(
        (const float4*)txt, txt16, N_TXT * DIM / 4);
    cudaEventRecord(ev_txt, sv);            // main's QK needs txt16
    splitv16_k<<<(DIM * DIM / 4 + 255) / 256, 256, 0, sv>>>(
        (const float4*)WV, wvh16, wvl16, DIM * DIM / 4);
    // Vt = (WVhi+WVlo) @ txt^T -> fp16 [DIM, N_TXT]
    proj2_gemm<<<dim3(N_TXT / 128, DIM / 128), 256, P2_SMEM, sv>>>(
        wvh16, wvl16, txt16, vt16, DIM, N_TXT, DIM);
    cudaEventRecord(ev_join, sv);

    // ---- main stream ----
    conv_img_k<<<(CN_MAIN + 255) / 256, 256>>>(
        (const float4*)img, img16, (float4*)rowsum);
    tconv_k<<<dim3(DIM / 32, HDIM / 32, 2), 256>>>(WQ, WK, wqT16, wkT16);

    // M1T[d2,d1] = sum_h Wk[h,d2] * Wq[h,d1]  = wkT @ wqT^T
    hgemm<1><<<dim3(DIM / 128, DIM / 128), 256, H_SMEM>>>(
        wkT16, wqT16, nullptr, m1t16, nullptr, DIM, DIM, HDIM);
    // A2 = img @ M1 = img @ m1t^T -> fp16 [N_IMG, DIM]
    hgemm<1><<<dim3(DIM / 128, N_IMG / 128), 256, H_SMEM>>>(
        img16, m1t16, nullptr, q16, nullptr, N_IMG, DIM, DIM);

    // QK needs txt16 from side stream
    cudaStreamWaitEvent(0, ev_txt, 0);
    // P~ = exp(A2@txt^T / 32 - 8) -> fp16, rowsum via atomics
    hgemm<2><<<dim3(N_TXT / 128, N_IMG / 128), 256, H_SMEM>>>(
        q16, txt16, nullptr, p16, rowsum, N_IMG, N_TXT, DIM);

    // ---- join: PV needs vt16 ----
    cudaStreamWaitEvent(0, ev_join, 0);
    // out = (P~ @ Vt^T) / rowsum[row] -> fp32
    hgemm<3><<<dim3(DIM / 128, N_IMG / 128), 256, H_SMEM>>>(
        p16, vt16, out, nullptr, rowsum, N_IMG, DIM, N_TXT);
}

// round 11
// speedup vs baseline: 1.4894x; 1.1007x over previous
#include <cuda_runtime.h>
#include <cuda_fp16.h>
#include <cstdint>

#define N_IMG 8192
#define N_TXT 8192
#define DIM   1024
#define HDIM  1024

// ---------------------------------------------------------------------------
// Device scratch (no allocations allowed)
// ---------------------------------------------------------------------------
__device__ __align__(1024) __half g_img16[(size_t)N_IMG * DIM];
__device__ __align__(1024) __half g_txt16[(size_t)N_TXT * DIM];
__device__ __align__(1024) __half g_wqT16[(size_t)DIM * HDIM];     // Wq^T [D,H]
__device__ __align__(1024) __half g_wkT16[(size_t)DIM * HDIM];     // Wk^T [D,H]
__device__ __align__(1024) __half g_m1t16[(size_t)DIM * DIM];      // (Wq^T Wk)^T
__device__ __align__(1024) __half g_wvh16[(size_t)DIM * DIM];      // fp16 hi of WV
__device__ __align__(1024) __half g_wvl16[(size_t)DIM * DIM];      // fp16 lo of WV
__device__ __align__(1024) __half g_q16 [(size_t)N_IMG * HDIM];    // A2 = img @ M1
__device__ __align__(1024) __half g_vt16[(size_t)DIM * N_TXT];
__device__ __align__(1024) __half g_p16 [(size_t)N_IMG * N_TXT];   // 128 MB
__device__ __align__(1024) float  g_rowsum[N_IMG];

// exp constants: exp(s*0.03125 - 8) = exp2(acc*c1 + c2)
#define EXP_C1 0.04508422f      // 0.03125 * log2(e)
#define EXP_C2 -11.54156036f    // -8 * log2(e)

// ---------------------------------------------------------------------------
// Portable PTX helpers
// ---------------------------------------------------------------------------
__device__ __forceinline__ uint32_t smem_to_u32(const void* p) {
    uint32_t a;
    asm("{ .reg .u64 t; cvta.to.shared.u64 t, %1; cvt.u32.u64 %0, t; }" : "=r"(a) : "l"(p));
    return a;
}
__device__ __forceinline__ void ldmatrix_x4(uint32_t* r, uint32_t addr) {
    asm volatile("ldmatrix.sync.aligned.m8n8.x4.shared.b16 {%0,%1,%2,%3}, [%4];"
        : "=r"(r[0]), "=r"(r[1]), "=r"(r[2]), "=r"(r[3]) : "r"(addr));
}
__device__ __forceinline__ void mma_fp16(float* c, const uint32_t* a, uint32_t b0, uint32_t b1) {
    asm volatile("mma.sync.aligned.m16n8k16.row.col.f32.f16.f16.f32 "
        "{%0,%1,%2,%3}, {%4,%5,%6,%7}, {%8,%9}, {%0,%1,%2,%3};"
        : "+f"(c[0]), "+f"(c[1]), "+f"(c[2]), "+f"(c[3])
        : "r"(a[0]), "r"(a[1]), "r"(a[2]), "r"(a[3]), "r"(b0), "r"(b1));
}
#define CP_ASYNC16(dst, src) \
    asm volatile("cp.async.cg.shared.global [%0], [%1], 16;" :: "r"(dst), "l"(src) : "memory")
#define CP_COMMIT() asm volatile("cp.async.commit_group;" ::: "memory")
#define CP_WAIT1()  asm volatile("cp.async.wait_group 1;" ::: "memory")

// ===========================================================================
// Tile loaders (K-major fp16, 64 cols = 128 B/row, swizzle c ^= r&7)
// ===========================================================================
__device__ __forceinline__ void load_tile64h(uint32_t dst, const __half* __restrict__ src,
                                             int ldK, int tid) {
#pragma unroll
    for (int i = 0; i < 4; i++) {
        int idx = tid + i * 256;
        int r = idx >> 3, c = idx & 7;
        int sc = c ^ (r & 7);
        CP_ASYNC16(dst + r * 128 + (sc << 4), src + (size_t)r * ldK + c * 8);
    }
}
__device__ __forceinline__ void load_tile64x64h(uint32_t dst, const __half* __restrict__ src,
                                                int ldK, int tid) {
#pragma unroll
    for (int i = 0; i < 2; i++) {
        int idx = tid + i * 256;
        int r = idx >> 3, c = idx & 7;
        int sc = c ^ (r & 7);
        CP_ASYNC16(dst + r * 128 + (sc << 4), src + (size_t)r * ldK + c * 8);
    }
}

// ===========================================================================
// Kernel A: 128x128 fp16 GEMM (MODE 1: C fp16) — M1 and A2 projections
// ===========================================================================
constexpr int H_TILE = 16384;
constexpr int H_OFF_A = 0, H_OFF_B = H_TILE;
constexpr int H_STG = 2 * H_TILE;
constexpr int H_NSTAGE = 3;
constexpr int H_SMEM = H_NSTAGE * H_STG;     // 96 KB

__global__ void __launch_bounds__(256, 1)
hgemm128(const __half* __restrict__ A, const __half* __restrict__ B,
         __half* __restrict__ Ch, int M, int N, int K)
{
    extern __shared__ __align__(1024) char smem[];
    const uint32_t sb = smem_to_u32(smem);
    const int tid  = threadIdx.x;
    const int lane = tid & 31;
    const int wid  = tid >> 5;
    const int wm   = wid & 1;
    const int wn   = wid >> 1;
    const int m0   = blockIdx.y * 128, n0 = blockIdx.x * 128;

    const __half* Ar = A + (size_t)m0 * K;
    const __half* Br = B + (size_t)n0 * K;

    float acc[4][4][4];
#pragma unroll
    for (int i = 0; i < 4; i++)
#pragma unroll
        for (int j = 0; j < 4; j++)
#pragma unroll
            for (int t = 0; t < 4; t++) acc[i][j][t] = 0.f;

    const int NK = K >> 6;

#pragma unroll
    for (int i = 0; i < H_NSTAGE - 1; i++) {
        if (i < NK) {
            uint32_t st = sb + i * H_STG;
            int ko = i * 64;
            load_tile64h(st + H_OFF_A, Ar + ko, K, tid);
            load_tile64h(st + H_OFF_B, Br + ko, K, tid);
        }
        CP_COMMIT();
    }

    const int lr = lane & 15;
    const int lc = lane >> 4;

    for (int k = 0; k < NK; k++) {
        CP_WAIT1();
        __syncthreads();

        int kn = k + H_NSTAGE - 1;
        if (kn < NK) {
            uint32_t st = sb + (kn % H_NSTAGE) * H_STG;
            int ko = kn * 64;
            load_tile64h(st + H_OFF_A, Ar + ko, K, tid);
            load_tile64h(st + H_OFF_B, Br + ko, K, tid);
        }
        CP_COMMIT();

        const uint32_t s = sb + (k % H_NSTAGE) * H_STG;
#pragma unroll
        for (int ks = 0; ks < 4; ks++) {
            uint32_t af[4][4], bfr[2][4];
#pragma unroll
            for (int mi = 0; mi < 4; mi++) {
                int r = wm * 64 + mi * 16 + lr;
                int c = ks * 2 + lc;
                int sc = c ^ (r & 7);
                ldmatrix_x4(af[mi], s + H_OFF_A + r * 128 + (sc << 4));
            }
#pragma unroll
            for (int nj = 0; nj < 2; nj++) {
                int r = wn * 32 + nj * 16 + lr;
                int c = ks * 2 + lc;
                int sc = c ^ (r & 7);
                ldmatrix_x4(bfr[nj], s + H_OFF_B + r * 128 + (sc << 4));
            }
#pragma unroll
            for (int mi = 0; mi < 4; mi++)
#pragma unroll
                for (int ni = 0; ni < 4; ni++) {
                    int nj = ni >> 1, hl = ni & 1;
                    mma_fp16(acc[mi][ni], af[mi], bfr[nj][hl], bfr[nj][2 + hl]);
                }
        }
    }

    const int er = (lane >> 2);
    const int ec = (lane & 3) * 2;
#pragma unroll
    for (int mi = 0; mi < 4; mi++)
#pragma unroll
        for (int ni = 0; ni < 4; ni++) {
            int row = m0 + wm * 64 + mi * 16 + er;
            int col = n0 + wn * 32 + ni * 8 + ec;
#pragma unroll
            for (int h = 0; h < 2; h++) {
                size_t off = (size_t)(row + 8 * h) * N + col;
                *reinterpret_cast<__half2*>(Ch + off) =
                    __floats2half2_rn(acc[mi][ni][2 * h], acc[mi][ni][2 * h + 1]);
            }
        }
}

// ===========================================================================
// Kernel B: 64x128 fp16 GEMM, 2 CTAs/SM — QK (MODE 2) and PV (MODE 3)
// ===========================================================================
constexpr int S64_OFF_A = 0, S64_OFF_B = 8192;    // A 8 KB, B 16 KB
constexpr int S64_STG = 24576;
constexpr int S64_NSTAGE = 3;
constexpr int S64_SMEM = S64_NSTAGE * S64_STG;    // 72 KB

template <int MODE>
__global__ void __launch_bounds__(256, 2)
hgemm64(const __half* __restrict__ A, const __half* __restrict__ B,
        float* __restrict__ Cf, __half* __restrict__ Ch,
        float* __restrict__ rowsum, int M, int N, int K)
{
    extern __shared__ __align__(1024) char smem[];
    const uint32_t sb = smem_to_u32(smem);
    const int tid  = threadIdx.x;
    const int lane = tid & 31;
    const int wid  = tid >> 5;
    const int wm   = wid & 1;     // 2 warp rows (32 rows each)
    const int wn   = wid >> 1;    // 4 warp cols (32 cols each)
    const int m0   = blockIdx.y * 64, n0 = blockIdx.x * 128;

    const __half* Ar = A + (size_t)m0 * K;
    const __half* Br = B + (size_t)n0 * K;

    float acc[2][4][4];
#pragma unroll
    for (int i = 0; i < 2; i++)
#pragma unroll
        for (int j = 0; j < 4; j++)
#pragma unroll
            for (int t = 0; t < 4; t++) acc[i][j][t] = 0.f;

    const int NK = K >> 6;

#pragma unroll
    for (int i = 0; i < S64_NSTAGE - 1; i++) {
        if (i < NK) {
            uint32_t st = sb + i * S64_STG;
            int ko = i * 64;
            load_tile64x64h(st + S64_OFF_A, Ar + ko, K, tid);
            load_tile64h(st + S64_OFF_B, Br + ko, K, tid);
        }
        CP_COMMIT();
    }

    const int lr = lane & 15;
    const int lc = lane >> 4;

    for (int k = 0; k < NK; k++) {
        CP_WAIT1();
        __syncthreads();

        int kn = k + S64_NSTAGE - 1;
        if (kn < NK) {
            uint32_t st = sb + (kn % S64_NSTAGE) * S64_STG;
            int ko = kn * 64;
            load_tile64x64h(st + S64_OFF_A, Ar + ko, K, tid);
            load_tile64h(st + S64_OFF_B, Br + ko, K, tid);
        }
        CP_COMMIT();

        const uint32_t s = sb + (k % S64_NSTAGE) * S64_STG;
#pragma unroll
        for (int ks = 0; ks < 4; ks++) {
            uint32_t af[2][4], bfr[2][4];
#pragma unroll
            for (int mi = 0; mi < 2; mi++) {
                int r = wm * 32 + mi * 16 + lr;
                int c = ks * 2 + lc;
                int sc = c ^ (r & 7);
                ldmatrix_x4(af[mi], s + S64_OFF_A + r * 128 + (sc << 4));
            }
#pragma unroll
            for (int nj = 0; nj < 2; nj++) {
                int r = wn * 32 + nj * 16 + lr;
                int c = ks * 2 + lc;
                int sc = c ^ (r & 7);
                ldmatrix_x4(bfr[nj], s + S64_OFF_B + r * 128 + (sc << 4));
            }
#pragma unroll
            for (int mi = 0; mi < 2; mi++)
#pragma unroll
                for (int ni = 0; ni < 4; ni++) {
                    int nj = ni >> 1, hl = ni & 1;
                    mma_fp16(acc[mi][ni], af[mi], bfr[nj][hl], bfr[nj][2 + hl]);
                }
        }
    }

    const int er = (lane >> 2);
    const int ec = (lane & 3) * 2;
#pragma unroll
    for (int mi = 0; mi < 2; mi++) {
        float rsum[2] = {0.f, 0.f};
        float rinv[2];
        if (MODE == 3) {
            rinv[0] = 1.0f / rowsum[m0 + wm * 32 + mi * 16 + er];
            rinv[1] = 1.0f / rowsum[m0 + wm * 32 + mi * 16 + er + 8];
        }
#pragma unroll
        for (int ni = 0; ni < 4; ni++) {
            int row = m0 + wm * 32 + mi * 16 + er;
            int col = n0 + wn * 32 + ni * 8 + ec;
#pragma unroll
            for (int h = 0; h < 2; h++) {
                float v0 = acc[mi][ni][2 * h + 0];
                float v1 = acc[mi][ni][2 * h + 1];
                size_t off = (size_t)(row + 8 * h) * N + col;
                if (MODE == 2) {
                    float e0 = exp2f(fmaf(v0, EXP_C1, EXP_C2));
                    float e1 = exp2f(fmaf(v1, EXP_C1, EXP_C2));
                    *reinterpret_cast<__half2*>(Ch + off) = __floats2half2_rn(e0, e1);
                    rsum[h] += e0 + e1;
                } else {   // MODE 3
                    *reinterpret_cast<float2*>(Cf + off) =
                        make_float2(v0 * rinv[h], v1 * rinv[h]);
                }
            }
        }
        if (MODE == 2) {
#pragma unroll
            for (int h = 0; h < 2; h++) {
                float v = rsum[h];
                v += __shfl_xor_sync(0xFFFFFFFFu, v, 1);
                v += __shfl_xor_sync(0xFFFFFFFFu, v, 2);
                if ((lane & 3) == 0)
                    atomicAdd(&rowsum[m0 + wm * 32 + mi * 16 + er + 8 * h], v);
            }
        }
    }
}

// ===========================================================================
// Kernel: 2-term fp16 GEMM (V projection): C = (Ahi+Alo)[M,K] @ B[N,K]^T
// ===========================================================================
constexpr int P2_OFF_AH = 0, P2_OFF_AL = 16384, P2_OFF_B = 32768;
constexpr int P2_STG = 3 * 16384;
constexpr int P2_NSTAGE = 3;
constexpr int P2_SMEM = P2_NSTAGE * P2_STG;  // 144 KB

__global__ void __launch_bounds__(256, 1)
proj2_gemm(const __half* __restrict__ Ahi, const __half* __restrict__ Alo,
           const __half* __restrict__ B, __half* __restrict__ C,
           int M, int N, int K)
{
    extern __shared__ __align__(1024) char smem[];
    const uint32_t sb = smem_to_u32(smem);
    const int tid  = threadIdx.x;
    const int lane = tid & 31;
    const int wid  = tid >> 5;
    const int wm   = wid & 1;
    const int wn   = wid >> 1;
    const int m0   = blockIdx.y * 128, n0 = blockIdx.x * 128;

    const __half* Ah = Ahi + (size_t)m0 * K;
    const __half* Al = Alo + (size_t)m0 * K;
    const __half* Br = B   + (size_t)n0 * K;

    float acc[4][4][4];
#pragma unroll
    for (int i = 0; i < 4; i++)
#pragma unroll
        for (int j = 0; j < 4; j++)
#pragma unroll
            for (int t = 0; t < 4; t++) acc[i][j][t] = 0.f;

    const int NK = K >> 6;

#pragma unroll
    for (int i = 0; i < P2_NSTAGE - 1; i++) {
        if (i < NK) {
            uint32_t st = sb + i * P2_STG;
            int ko = i * 64;
            load_tile64h(st + P2_OFF_AH, Ah + ko, K, tid);
            load_tile64h(st + P2_OFF_AL, Al + ko, K, tid);
            load_tile64h(st + P2_OFF_B,  Br + ko, K, tid);
        }
        CP_COMMIT();
    }

    const int lr = lane & 15;
    const int lc = lane >> 4;

    for (int k = 0; k < NK; k++) {
        CP_WAIT1();
        __syncthreads();

        int kn = k + P2_NSTAGE - 1;
        if (kn < NK) {
            uint32_t st = sb + (kn % P2_NSTAGE) * P2_STG;
            int ko = kn * 64;
            load_tile64h(st + P2_OFF_AH, Ah + ko, K, tid);
            load_tile64h(st + P2_OFF_AL, Al + ko, K, tid);
            load_tile64h(st + P2_OFF_B,  Br + ko, K, tid);
        }
        CP_COMMIT();

        const uint32_t s = sb + (k % P2_NSTAGE) * P2_STG;
#pragma unroll
        for (int ks = 0; ks < 4; ks++) {
            uint32_t ah[4][4], al[4][4], bfr[2][4];
#pragma unroll
            for (int mi = 0; mi < 4; mi++) {
                int r = wm * 64 + mi * 16 + lr;
                int c = ks * 2 + lc;
                int sc = c ^ (r & 7);
                ldmatrix_x4(ah[mi], s + P2_OFF_AH + r * 128 + (sc << 4));
                ldmatrix_x4(al[mi], s + P2_OFF_AL + r * 128 + (sc << 4));
            }
#pragma unroll
            for (int nj = 0; nj < 2; nj++) {
                int r = wn * 32 + nj * 16 + lr;
                int c = ks * 2 + lc;
                int sc = c ^ (r & 7);
                ldmatrix_x4(bfr[nj], s + P2_OFF_B + r * 128 + (sc << 4));
            }
#pragma unroll
            for (int mi = 0; mi < 4; mi++)
#pragma unroll
                for (int ni = 0; ni < 4; ni++) {
                    int nj = ni >> 1, hl = ni & 1;
                    mma_fp16(acc[mi][ni], ah[mi], bfr[nj][hl], bfr[nj][2 + hl]);
                    mma_fp16(acc[mi][ni], al[mi], bfr[nj][hl], bfr[nj][2 + hl]);
                }
        }
    }

    const int er = (lane >> 2);
    const int ec = (lane & 3) * 2;
#pragma unroll
    for (int mi = 0; mi < 4; mi++)
#pragma unroll
        for (int ni = 0; ni < 4; ni++) {
            int row = m0 + wm * 64 + mi * 16 + er;
            int col = n0 + wn * 32 + ni * 8 + ec;
#pragma unroll
            for (int h = 0; h < 2; h++) {
                size_t off = (size_t)(row + 8 * h) * N + col;
                *reinterpret_cast<__half2*>(C + off) =
                    __floats2half2_rn(acc[mi][ni][2 * h], acc[mi][ni][2 * h + 1]);
            }
        }
}

// ---------------------------------------------------------------------------
// img fp32->fp16 + rowsum zeroing (main stream)
// ---------------------------------------------------------------------------
constexpr int CN_IMG = N_IMG * DIM / 4;
constexpr int CN_RS  = N_IMG / 4;
constexpr int CN_MAIN = CN_IMG + CN_RS;

__global__ void __launch_bounds__(256)
conv_img_k(const float4* __restrict__ img, __half* __restrict__ img16,
           float4* __restrict__ rowsum)
{
    int i = blockIdx.x * blockDim.x + threadIdx.x;
    if (i < CN_IMG) {
        float4 v = img[i];
        __half2* p = reinterpret_cast<__half2*>(img16 + (size_t)i * 4);
        p[0] = __floats2half2_rn(v.x, v.y);
        p[1] = __floats2half2_rn(v.z, v.w);
    } else if (i - CN_IMG < CN_RS) {
        rowsum[i - CN_IMG] = make_float4(0.f, 0.f, 0.f, 0.f);
    }
}

__global__ void __launch_bounds__(256)
conv16_k(const float4* __restrict__ x, __half* __restrict__ y, int n4)
{
    int i = blockIdx.x * blockDim.x + threadIdx.x;
    if (i >= n4) return;
    float4 v = x[i];
    __half2* p = reinterpret_cast<__half2*>(y + (size_t)i * 4);
    p[0] = __floats2half2_rn(v.x, v.y);
    p[1] = __floats2half2_rn(v.z, v.w);
}

// ---------------------------------------------------------------------------
// Wq/Wk fp32 -> fp16 TRANSPOSED (smem tiled); z selects which weight
// ---------------------------------------------------------------------------
__global__ void __launch_bounds__(256)
tconv_k(const float* __restrict__ wq, const float* __restrict__ wk,
        __half* __restrict__ wqT, __half* __restrict__ wkT)
{
    __shared__ float tile[32][33];
    const float* src = blockIdx.z ? wk : wq;
    __half* dst = blockIdx.z ? wkT : wqT;
    int x0 = blockIdx.x * 32;
    int y0 = blockIdx.y * 32;
    int tx = threadIdx.x & 31, ty = threadIdx.x >> 5;
#pragma unroll
    for (int i = 0; i < 4; i++)
        tile[ty + i * 8][tx] = src[(size_t)(y0 + ty + i * 8) * DIM + x0 + tx];
    __syncthreads();
#pragma unroll
    for (int i = 0; i < 4; i++)
        dst[(size_t)(x0 + ty + i * 8) * HDIM + y0 + tx] =
            __float2half_rn(tile[tx][ty + i * 8]);
}

// ---------------------------------------------------------------------------
// WV fp32 -> fp16 (hi, lo) split (side stream)
// ---------------------------------------------------------------------------
__global__ void __launch_bounds__(256)
splitv16_k(const float4* __restrict__ x, __half* __restrict__ hi,
           __half* __restrict__ lo, int n4)
{
    int i = blockIdx.x * blockDim.x + threadIdx.x;
    if (i >= n4) return;
    float4 v = x[i];
    float f[4] = {v.x, v.y, v.z, v.w};
    __half h[4], l[4];
#pragma unroll
    for (int j = 0; j < 4; j++) {
        h[j] = __float2half_rn(f[j]);
        l[j] = __float2half_rn(f[j] - __half2float(h[j]));
    }
    __half2* ph = reinterpret_cast<__half2*>(hi + (size_t)i * 4);
    __half2* pl = reinterpret_cast<__half2*>(lo + (size_t)i * 4);
    ph[0] = __half2(h[0], h[1]); ph[1] = __half2(h[2], h[3]);
    pl[0] = __half2(l[0], l[1]); pl[1] = __half2(l[2], l[3]);
}

// ---------------------------------------------------------------------------
extern "C" void kernel_launch(void* const* d_in, const int* in_sizes, int n_in,
                              void* d_out, int out_size)
{
    const float* img = (const float*)d_in[0];   // [N_IMG, DIM]
    const float* txt = (const float*)d_in[1];   // [N_TXT, DIM]
    const float* WQ  = (const float*)d_in[2];   // [HDIM, DIM]
    const float* WK  = (const float*)d_in[3];   // [HDIM, DIM]
    const float* WV  = (const float*)d_in[4];   // [DIM, DIM]
    float* out = (float*)d_out;                 // [N_IMG, DIM]

    static bool init_done = false;
    static cudaStream_t sv = nullptr;
    static cudaEvent_t ev_fork = nullptr, ev_txt = nullptr, ev_join = nullptr;
    if (!init_done) {
        cudaFuncSetAttribute(hgemm128,   cudaFuncAttributeMaxDynamicSharedMemorySize, H_SMEM);
        cudaFuncSetAttribute(hgemm64<2>, cudaFuncAttributeMaxDynamicSharedMemorySize, S64_SMEM);
        cudaFuncSetAttribute(hgemm64<3>, cudaFuncAttributeMaxDynamicSharedMemorySize, S64_SMEM);
        cudaFuncSetAttribute(proj2_gemm, cudaFuncAttributeMaxDynamicSharedMemorySize, P2_SMEM);
        cudaStreamCreateWithFlags(&sv, cudaStreamNonBlocking);
        cudaEventCreateWithFlags(&ev_fork, cudaEventDisableTiming);
        cudaEventCreateWithFlags(&ev_txt,  cudaEventDisableTiming);
        cudaEventCreateWithFlags(&ev_join, cudaEventDisableTiming);
        init_done = true;
    }

    __half *img16, *txt16, *wqT16, *wkT16, *m1t16, *wvh16, *wvl16, *q16, *vt16, *p16;
    float *rowsum;
    cudaGetSymbolAddress((void**)&img16, g_img16);
    cudaGetSymbolAddress((void**)&txt16, g_txt16);
    cudaGetSymbolAddress((void**)&wqT16, g_wqT16);
    cudaGetSymbolAddress((void**)&wkT16, g_wkT16);
    cudaGetSymbolAddress((void**)&m1t16, g_m1t16);
    cudaGetSymbolAddress((void**)&wvh16, g_wvh16);
    cudaGetSymbolAddress((void**)&wvl16, g_wvl16);
    cudaGetSymbolAddress((void**)&q16, g_q16);
    cudaGetSymbolAddress((void**)&vt16, g_vt16);
    cudaGetSymbolAddress((void**)&p16, g_p16);
    cudaGetSymbolAddress((void**)&rowsum, g_rowsum);

    // ---- fork: side stream = txt conv + V chain ----
    cudaEventRecord(ev_fork, 0);
    cudaStreamWaitEvent(sv, ev_fork, 0);
    conv16_k<<<(N_TXT * DIM / 4 + 255) / 256, 256, 0, sv>>>(
        (const float4*)txt, txt16, N_TXT * DIM / 4);
    cudaEventRecord(ev_txt, sv);            // main's QK needs txt16
    splitv16_k<<<(DIM * DIM / 4 + 255) / 256, 256, 0, sv>>>(
        (const float4*)WV, wvh16, wvl16, DIM * DIM / 4);
    // Vt = (WVhi+WVlo) @ txt^T -> fp16 [DIM, N_TXT]
    proj2_gemm<<<dim3(N_TXT / 128, DIM / 128), 256, P2_SMEM, sv>>>(
        wvh16, wvl16, txt16, vt16, DIM, N_TXT, DIM);
    cudaEventRecord(ev_join, sv);

    // ---- main stream ----
    conv_img_k<<<(CN_MAIN + 255) / 256, 256>>>(
        (const float4*)img, img16, (float4*)rowsum);
    tconv_k<<<dim3(DIM / 32, HDIM / 32, 2), 256>>>(WQ, WK, wqT16, wkT16);

    // M1T = wkT @ wqT^T  [DIM, DIM]
    hgemm128<<<dim3(DIM / 128, DIM / 128), 256, H_SMEM>>>(
        wkT16, wqT16, m1t16, DIM, DIM, HDIM);
    // A2 = img @ M1 = img @ m1t^T -> fp16 [N_IMG, DIM]
    hgemm128<<<dim3(DIM / 128, N_IMG / 128), 256, H_SMEM>>>(
        img16, m1t16, q16, N_IMG, DIM, DIM);

    // QK needs txt16 from side stream
    cudaStreamWaitEvent(0, ev_txt, 0);
    // P~ = exp(A2@txt^T / 32 - 8) -> fp16, rowsum via atomics  (64-row tiles)
    hgemm64<2><<<dim3(N_TXT / 128, N_IMG / 64), 256, S64_SMEM>>>(
        q16, txt16, nullptr, p16, rowsum, N_IMG, N_TXT, DIM);

    // ---- join: PV needs vt16 ----
    cudaStreamWaitEvent(0, ev_join, 0);
    // out = (P~ @ Vt^T) / rowsum[row] -> fp32  (64-row tiles, 2 CTA/SM)
    hgemm64<3><<<dim3(DIM / 128, N_IMG / 64), 256, S64_SMEM>>>(
        p16, vt16, out, nullptr, rowsum, N_IMG, DIM, N_TXT);
}

// round 12
// speedup vs baseline: 1.5486x; 1.0397x over previous
#include <cuda_runtime.h>
#include <cuda_fp16.h>
#include <cstdint>

#define N_IMG 8192
#define N_TXT 8192
#define DIM   1024
#define HDIM  1024

// ---------------------------------------------------------------------------
// Device scratch (no allocations allowed)
// ---------------------------------------------------------------------------
__device__ __align__(1024) __half g_img16[(size_t)N_IMG * DIM];
__device__ __align__(1024) __half g_txt16[(size_t)N_TXT * DIM];
__device__ __align__(1024) __half g_wqT16[(size_t)DIM * HDIM];     // Wq^T [D,H]
__device__ __align__(1024) __half g_wkT16[(size_t)DIM * HDIM];     // Wk^T [D,H]
__device__ __align__(1024) __half g_m1t16[(size_t)DIM * DIM];      // (Wq^T Wk)^T
__device__ __align__(1024) __half g_wv16 [(size_t)DIM * DIM];      // fp16 WV
__device__ __align__(1024) __half g_q16 [(size_t)N_IMG * HDIM];    // A2 = img @ M1
__device__ __align__(1024) __half g_vt16[(size_t)DIM * N_TXT];
__device__ __align__(1024) __half g_p16 [(size_t)N_IMG * N_TXT];   // 128 MB
__device__ __align__(1024) float  g_rowsum[N_IMG];

// exp constants: exp(s*0.03125 - 8) = exp2(acc*c1 + c2)
#define EXP_C1 0.04508422f      // 0.03125 * log2(e)
#define EXP_C2 -11.54156036f    // -8 * log2(e)

// ---------------------------------------------------------------------------
// Portable PTX helpers
// ---------------------------------------------------------------------------
__device__ __forceinline__ uint32_t smem_to_u32(const void* p) {
    uint32_t a;
    asm("{ .reg .u64 t; cvta.to.shared.u64 t, %1; cvt.u32.u64 %0, t; }" : "=r"(a) : "l"(p));
    return a;
}
__device__ __forceinline__ void ldmatrix_x4(uint32_t* r, uint32_t addr) {
    asm volatile("ldmatrix.sync.aligned.m8n8.x4.shared.b16 {%0,%1,%2,%3}, [%4];"
        : "=r"(r[0]), "=r"(r[1]), "=r"(r[2]), "=r"(r[3]) : "r"(addr));
}
__device__ __forceinline__ void mma_fp16(float* c, const uint32_t* a, uint32_t b0, uint32_t b1) {
    asm volatile("mma.sync.aligned.m16n8k16.row.col.f32.f16.f16.f32 "
        "{%0,%1,%2,%3}, {%4,%5,%6,%7}, {%8,%9}, {%0,%1,%2,%3};"
        : "+f"(c[0]), "+f"(c[1]), "+f"(c[2]), "+f"(c[3])
        : "r"(a[0]), "r"(a[1]), "r"(a[2]), "r"(a[3]), "r"(b0), "r"(b1));
}
#define CP_ASYNC16(dst, src) \
    asm volatile("cp.async.cg.shared.global [%0], [%1], 16;" :: "r"(dst), "l"(src) : "memory")
#define CP_COMMIT() asm volatile("cp.async.commit_group;" ::: "memory")
#define CP_WAIT1()  asm volatile("cp.async.wait_group 1;" ::: "memory")

// ===========================================================================
// Tile loaders (K-major fp16, 64 cols = 128 B/row, swizzle c ^= r&7)
// ===========================================================================
__device__ __forceinline__ void load_tile64h(uint32_t dst, const __half* __restrict__ src,
                                             int ldK, int tid) {
#pragma unroll
    for (int i = 0; i < 4; i++) {
        int idx = tid + i * 256;
        int r = idx >> 3, c = idx & 7;
        int sc = c ^ (r & 7);
        CP_ASYNC16(dst + r * 128 + (sc << 4), src + (size_t)r * ldK + c * 8);
    }
}
__device__ __forceinline__ void load_tile64x64h(uint32_t dst, const __half* __restrict__ src,
                                                int ldK, int tid) {
#pragma unroll
    for (int i = 0; i < 2; i++) {
        int idx = tid + i * 256;
        int r = idx >> 3, c = idx & 7;
        int sc = c ^ (r & 7);
        CP_ASYNC16(dst + r * 128 + (sc << 4), src + (size_t)r * ldK + c * 8);
    }
}

// ===========================================================================
// Kernel A: 128x128 fp16 GEMM (C fp16) — M1 only (tiny)
// ===========================================================================
constexpr int H_TILE = 16384;
constexpr int H_OFF_A = 0, H_OFF_B = H_TILE;
constexpr int H_STG = 2 * H_TILE;
constexpr int H_NSTAGE = 3;
constexpr int H_SMEM = H_NSTAGE * H_STG;     // 96 KB

__global__ void __launch_bounds__(256, 1)
hgemm128(const __half* __restrict__ A, const __half* __restrict__ B,
         __half* __restrict__ Ch, int M, int N, int K)
{
    extern __shared__ __align__(1024) char smem[];
    const uint32_t sb = smem_to_u32(smem);
    const int tid  = threadIdx.x;
    const int lane = tid & 31;
    const int wid  = tid >> 5;
    const int wm   = wid & 1;
    const int wn   = wid >> 1;
    const int m0   = blockIdx.y * 128, n0 = blockIdx.x * 128;

    const __half* Ar = A + (size_t)m0 * K;
    const __half* Br = B + (size_t)n0 * K;

    float acc[4][4][4];
#pragma unroll
    for (int i = 0; i < 4; i++)
#pragma unroll
        for (int j = 0; j < 4; j++)
#pragma unroll
            for (int t = 0; t < 4; t++) acc[i][j][t] = 0.f;

    const int NK = K >> 6;

#pragma unroll
    for (int i = 0; i < H_NSTAGE - 1; i++) {
        if (i < NK) {
            uint32_t st = sb + i * H_STG;
            int ko = i * 64;
            load_tile64h(st + H_OFF_A, Ar + ko, K, tid);
            load_tile64h(st + H_OFF_B, Br + ko, K, tid);
        }
        CP_COMMIT();
    }

    const int lr = lane & 15;
    const int lc = lane >> 4;

    for (int k = 0; k < NK; k++) {
        CP_WAIT1();
        __syncthreads();

        int kn = k + H_NSTAGE - 1;
        if (kn < NK) {
            uint32_t st = sb + (kn % H_NSTAGE) * H_STG;
            int ko = kn * 64;
            load_tile64h(st + H_OFF_A, Ar + ko, K, tid);
            load_tile64h(st + H_OFF_B, Br + ko, K, tid);
        }
        CP_COMMIT();

        const uint32_t s = sb + (k % H_NSTAGE) * H_STG;
#pragma unroll
        for (int ks = 0; ks < 4; ks++) {
            uint32_t af[4][4], bfr[2][4];
#pragma unroll
            for (int mi = 0; mi < 4; mi++) {
                int r = wm * 64 + mi * 16 + lr;
                int c = ks * 2 + lc;
                int sc = c ^ (r & 7);
                ldmatrix_x4(af[mi], s + H_OFF_A + r * 128 + (sc << 4));
            }
#pragma unroll
            for (int nj = 0; nj < 2; nj++) {
                int r = wn * 32 + nj * 16 + lr;
                int c = ks * 2 + lc;
                int sc = c ^ (r & 7);
                ldmatrix_x4(bfr[nj], s + H_OFF_B + r * 128 + (sc << 4));
            }
#pragma unroll
            for (int mi = 0; mi < 4; mi++)
#pragma unroll
                for (int ni = 0; ni < 4; ni++) {
                    int nj = ni >> 1, hl = ni & 1;
                    mma_fp16(acc[mi][ni], af[mi], bfr[nj][hl], bfr[nj][2 + hl]);
                }
        }
    }

    const int er = (lane >> 2);
    const int ec = (lane & 3) * 2;
#pragma unroll
    for (int mi = 0; mi < 4; mi++)
#pragma unroll
        for (int ni = 0; ni < 4; ni++) {
            int row = m0 + wm * 64 + mi * 16 + er;
            int col = n0 + wn * 32 + ni * 8 + ec;
#pragma unroll
            for (int h = 0; h < 2; h++) {
                size_t off = (size_t)(row + 8 * h) * N + col;
                *reinterpret_cast<__half2*>(Ch + off) =
                    __floats2half2_rn(acc[mi][ni][2 * h], acc[mi][ni][2 * h + 1]);
            }
        }
}

// ===========================================================================
// Kernel B: 64x128 fp16 GEMM, 2 CTAs/SM — A2/Vt (MODE 1), QK (2), PV (3)
// ===========================================================================
constexpr int S64_OFF_A = 0, S64_OFF_B = 8192;    // A 8 KB, B 16 KB
constexpr int S64_STG = 24576;
constexpr int S64_NSTAGE = 3;
constexpr int S64_SMEM = S64_NSTAGE * S64_STG;    // 72 KB

template <int MODE>
__global__ void __launch_bounds__(256, 2)
hgemm64(const __half* __restrict__ A, const __half* __restrict__ B,
        float* __restrict__ Cf, __half* __restrict__ Ch,
        float* __restrict__ rowsum, int M, int N, int K)
{
    extern __shared__ __align__(1024) char smem[];
    const uint32_t sb = smem_to_u32(smem);
    const int tid  = threadIdx.x;
    const int lane = tid & 31;
    const int wid  = tid >> 5;
    const int wm   = wid & 1;     // 2 warp rows (32 rows each)
    const int wn   = wid >> 1;    // 4 warp cols (32 cols each)
    const int m0   = blockIdx.y * 64, n0 = blockIdx.x * 128;

    const __half* Ar = A + (size_t)m0 * K;
    const __half* Br = B + (size_t)n0 * K;

    float acc[2][4][4];
#pragma unroll
    for (int i = 0; i < 2; i++)
#pragma unroll
        for (int j = 0; j < 4; j++)
#pragma unroll
            for (int t = 0; t < 4; t++) acc[i][j][t] = 0.f;

    const int NK = K >> 6;

#pragma unroll
    for (int i = 0; i < S64_NSTAGE - 1; i++) {
        if (i < NK) {
            uint32_t st = sb + i * S64_STG;
            int ko = i * 64;
            load_tile64x64h(st + S64_OFF_A, Ar + ko, K, tid);
            load_tile64h(st + S64_OFF_B, Br + ko, K, tid);
        }
        CP_COMMIT();
    }

    const int lr = lane & 15;
    const int lc = lane >> 4;

    for (int k = 0; k < NK; k++) {
        CP_WAIT1();
        __syncthreads();

        int kn = k + S64_NSTAGE - 1;
        if (kn < NK) {
            uint32_t st = sb + (kn % S64_NSTAGE) * S64_STG;
            int ko = kn * 64;
            load_tile64x64h(st + S64_OFF_A, Ar + ko, K, tid);
            load_tile64h(st + S64_OFF_B, Br + ko, K, tid);
        }
        CP_COMMIT();

        const uint32_t s = sb + (k % S64_NSTAGE) * S64_STG;
#pragma unroll
        for (int ks = 0; ks < 4; ks++) {
            uint32_t af[2][4], bfr[2][4];
#pragma unroll
            for (int mi = 0; mi < 2; mi++) {
                int r = wm * 32 + mi * 16 + lr;
                int c = ks * 2 + lc;
                int sc = c ^ (r & 7);
                ldmatrix_x4(af[mi], s + S64_OFF_A + r * 128 + (sc << 4));
            }
#pragma unroll
            for (int nj = 0; nj < 2; nj++) {
                int r = wn * 32 + nj * 16 + lr;
                int c = ks * 2 + lc;
                int sc = c ^ (r & 7);
                ldmatrix_x4(bfr[nj], s + S64_OFF_B + r * 128 + (sc << 4));
            }
#pragma unroll
            for (int mi = 0; mi < 2; mi++)
#pragma unroll
                for (int ni = 0; ni < 4; ni++) {
                    int nj = ni >> 1, hl = ni & 1;
                    mma_fp16(acc[mi][ni], af[mi], bfr[nj][hl], bfr[nj][2 + hl]);
                }
        }
    }

    const int er = (lane >> 2);
    const int ec = (lane & 3) * 2;
#pragma unroll
    for (int mi = 0; mi < 2; mi++) {
        float rsum[2] = {0.f, 0.f};
        float rinv[2];
        if (MODE == 3) {
            rinv[0] = 1.0f / rowsum[m0 + wm * 32 + mi * 16 + er];
            rinv[1] = 1.0f / rowsum[m0 + wm * 32 + mi * 16 + er + 8];
        }
#pragma unroll
        for (int ni = 0; ni < 4; ni++) {
            int row = m0 + wm * 32 + mi * 16 + er;
            int col = n0 + wn * 32 + ni * 8 + ec;
#pragma unroll
            for (int h = 0; h < 2; h++) {
                float v0 = acc[mi][ni][2 * h + 0];
                float v1 = acc[mi][ni][2 * h + 1];
                size_t off = (size_t)(row + 8 * h) * N + col;
                if (MODE == 1) {
                    *reinterpret_cast<__half2*>(Ch + off) = __floats2half2_rn(v0, v1);
                } else if (MODE == 2) {
                    float e0 = exp2f(fmaf(v0, EXP_C1, EXP_C2));
                    float e1 = exp2f(fmaf(v1, EXP_C1, EXP_C2));
                    *reinterpret_cast<__half2*>(Ch + off) = __floats2half2_rn(e0, e1);
                    rsum[h] += e0 + e1;
                } else {   // MODE 3
                    *reinterpret_cast<float2*>(Cf + off) =
                        make_float2(v0 * rinv[h], v1 * rinv[h]);
                }
            }
        }
        if (MODE == 2) {
#pragma unroll
            for (int h = 0; h < 2; h++) {
                float v = rsum[h];
                v += __shfl_xor_sync(0xFFFFFFFFu, v, 1);
                v += __shfl_xor_sync(0xFFFFFFFFu, v, 2);
                if ((lane & 3) == 0)
                    atomicAdd(&rowsum[m0 + wm * 32 + mi * 16 + er + 8 * h], v);
            }
        }
    }
}

// ---------------------------------------------------------------------------
// img fp32->fp16 + rowsum zeroing (main stream)
// ---------------------------------------------------------------------------
constexpr int CN_IMG = N_IMG * DIM / 4;
constexpr int CN_RS  = N_IMG / 4;
constexpr int CN_MAIN = CN_IMG + CN_RS;

__global__ void __launch_bounds__(256)
conv_img_k(const float4* __restrict__ img, __half* __restrict__ img16,
           float4* __restrict__ rowsum)
{
    int i = blockIdx.x * blockDim.x + threadIdx.x;
    if (i < CN_IMG) {
        float4 v = img[i];
        __half2* p = reinterpret_cast<__half2*>(img16 + (size_t)i * 4);
        p[0] = __floats2half2_rn(v.x, v.y);
        p[1] = __floats2half2_rn(v.z, v.w);
    } else if (i - CN_IMG < CN_RS) {
        rowsum[i - CN_IMG] = make_float4(0.f, 0.f, 0.f, 0.f);
    }
}

__global__ void __launch_bounds__(256)
conv16_k(const float4* __restrict__ x, __half* __restrict__ y, int n4)
{
    int i = blockIdx.x * blockDim.x + threadIdx.x;
    if (i >= n4) return;
    float4 v = x[i];
    __half2* p = reinterpret_cast<__half2*>(y + (size_t)i * 4);
    p[0] = __floats2half2_rn(v.x, v.y);
    p[1] = __floats2half2_rn(v.z, v.w);
}

// ---------------------------------------------------------------------------
// Wq/Wk fp32 -> fp16 TRANSPOSED (smem tiled); z selects which weight
// ---------------------------------------------------------------------------
__global__ void __launch_bounds__(256)
tconv_k(const float* __restrict__ wq, const float* __restrict__ wk,
        __half* __restrict__ wqT, __half* __restrict__ wkT)
{
    __shared__ float tile[32][33];
    const float* src = blockIdx.z ? wk : wq;
    __half* dst = blockIdx.z ? wkT : wqT;
    int x0 = blockIdx.x * 32;
    int y0 = blockIdx.y * 32;
    int tx = threadIdx.x & 31, ty = threadIdx.x >> 5;
#pragma unroll
    for (int i = 0; i < 4; i++)
        tile[ty + i * 8][tx] = src[(size_t)(y0 + ty + i * 8) * DIM + x0 + tx];
    __syncthreads();
#pragma unroll
    for (int i = 0; i < 4; i++)
        dst[(size_t)(x0 + ty + i * 8) * HDIM + y0 + tx] =
            __float2half_rn(tile[tx][ty + i * 8]);
}

// ---------------------------------------------------------------------------
extern "C" void kernel_launch(void* const* d_in, const int* in_sizes, int n_in,
                              void* d_out, int out_size)
{
    const float* img = (const float*)d_in[0];   // [N_IMG, DIM]
    const float* txt = (const float*)d_in[1];   // [N_TXT, DIM]
    const float* WQ  = (const float*)d_in[2];   // [HDIM, DIM]
    const float* WK  = (const float*)d_in[3];   // [HDIM, DIM]
    const float* WV  = (const float*)d_in[4];   // [DIM, DIM]
    float* out = (float*)d_out;                 // [N_IMG, DIM]

    static bool init_done = false;
    static cudaStream_t sv = nullptr;
    static cudaEvent_t ev_fork = nullptr, ev_txt = nullptr, ev_join = nullptr;
    if (!init_done) {
        cudaFuncSetAttribute(hgemm128,   cudaFuncAttributeMaxDynamicSharedMemorySize, H_SMEM);
        cudaFuncSetAttribute(hgemm64<1>, cudaFuncAttributeMaxDynamicSharedMemorySize, S64_SMEM);
        cudaFuncSetAttribute(hgemm64<2>, cudaFuncAttributeMaxDynamicSharedMemorySize, S64_SMEM);
        cudaFuncSetAttribute(hgemm64<3>, cudaFuncAttributeMaxDynamicSharedMemorySize, S64_SMEM);
        cudaStreamCreateWithFlags(&sv, cudaStreamNonBlocking);
        cudaEventCreateWithFlags(&ev_fork, cudaEventDisableTiming);
        cudaEventCreateWithFlags(&ev_txt,  cudaEventDisableTiming);
        cudaEventCreateWithFlags(&ev_join, cudaEventDisableTiming);
        init_done = true;
    }

    __half *img16, *txt16, *wqT16, *wkT16, *m1t16, *wv16, *q16, *vt16, *p16;
    float *rowsum;
    cudaGetSymbolAddress((void**)&img16, g_img16);
    cudaGetSymbolAddress((void**)&txt16, g_txt16);
    cudaGetSymbolAddress((void**)&wqT16, g_wqT16);
    cudaGetSymbolAddress((void**)&wkT16, g_wkT16);
    cudaGetSymbolAddress((void**)&m1t16, g_m1t16);
    cudaGetSymbolAddress((void**)&wv16, g_wv16);
    cudaGetSymbolAddress((void**)&q16, g_q16);
    cudaGetSymbolAddress((void**)&vt16, g_vt16);
    cudaGetSymbolAddress((void**)&p16, g_p16);
    cudaGetSymbolAddress((void**)&rowsum, g_rowsum);

    // ---- fork: side stream = txt conv + V chain ----
    cudaEventRecord(ev_fork, 0);
    cudaStreamWaitEvent(sv, ev_fork, 0);
    conv16_k<<<(N_TXT * DIM / 4 + 255) / 256, 256, 0, sv>>>(
        (const float4*)txt, txt16, N_TXT * DIM / 4);
    cudaEventRecord(ev_txt, sv);            // main's QK needs txt16
    conv16_k<<<(DIM * DIM / 4 + 255) / 256, 256, 0, sv>>>(
        (const float4*)WV, wv16, DIM * DIM / 4);
    // Vt = WV @ txt^T -> fp16 [DIM, N_TXT]  (1-term fp16, 64-row tiles)
    hgemm64<1><<<dim3(N_TXT / 128, DIM / 64), 256, S64_SMEM, sv>>>(
        wv16, txt16, nullptr, vt16, nullptr, DIM, N_TXT, DIM);
    cudaEventRecord(ev_join, sv);

    // ---- main stream ----
    conv_img_k<<<(CN_MAIN + 255) / 256, 256>>>(
        (const float4*)img, img16, (float4*)rowsum);
    tconv_k<<<dim3(DIM / 32, HDIM / 32, 2), 256>>>(WQ, WK, wqT16, wkT16);

    // M1T = wkT @ wqT^T  [DIM, DIM]
    hgemm128<<<dim3(DIM / 128, DIM / 128), 256, H_SMEM>>>(
        wkT16, wqT16, m1t16, DIM, DIM, HDIM);
    // A2 = img @ M1 = img @ m1t^T -> fp16 [N_IMG, DIM]  (64-row tiles)
    hgemm64<1><<<dim3(DIM / 128, N_IMG / 64), 256, S64_SMEM>>>(
        img16, m1t16, nullptr, q16, nullptr, N_IMG, DIM, DIM);

    // QK needs txt16 from side stream
    cudaStreamWaitEvent(0, ev_txt, 0);
    // P~ = exp(A2@txt^T / 32 - 8) -> fp16, rowsum via atomics
    hgemm64<2><<<dim3(N_TXT / 128, N_IMG / 64), 256, S64_SMEM>>>(
        q16, txt16, nullptr, p16, rowsum, N_IMG, N_TXT, DIM);

    // ---- join: PV needs vt16 ----
    cudaStreamWaitEvent(0, ev_join, 0);
    // out = (P~ @ Vt^T) / rowsum[row] -> fp32
    hgemm64<3><<<dim3(DIM / 128, N_IMG / 64), 256, S64_SMEM>>>(
        p16, vt16, out, nullptr, rowsum, N_IMG, DIM, N_TXT);
}

// round 13
// speedup vs baseline: 1.5708x; 1.0144x over previous
#include <cuda_runtime.h>
#include <cuda_fp16.h>
#include <cstdint>

#define N_IMG 8192
#define N_TXT 8192
#define DIM   1024
#define HDIM  1024

// ---------------------------------------------------------------------------
// Device scratch (no allocations allowed)
// ---------------------------------------------------------------------------
__device__ __align__(1024) __half g_img16[(size_t)N_IMG * DIM];
__device__ __align__(1024) __half g_txt16[(size_t)N_TXT * DIM];
__device__ __align__(1024) __half g_wqT16[(size_t)DIM * HDIM];     // Wq^T [D,H]
__device__ __align__(1024) __half g_wkT16[(size_t)DIM * HDIM];     // Wk^T [D,H]
__device__ __align__(1024) __half g_m1t16[(size_t)DIM * DIM];      // (Wq^T Wk)^T
__device__ __align__(1024) __half g_wv16 [(size_t)DIM * DIM];      // fp16 WV
__device__ __align__(1024) __half g_q16 [(size_t)N_IMG * HDIM];    // A2 = img @ M1
__device__ __align__(1024) __half g_vt16[(size_t)DIM * N_TXT];
__device__ __align__(1024) __half g_p16 [(size_t)N_IMG * N_TXT];   // 128 MB
__device__ __align__(1024) float  g_rowsum[N_IMG];

// exp constants: exp(s*0.03125 - 8) = exp2(acc*c1 + c2)
#define EXP_C1 0.04508422f      // 0.03125 * log2(e)
#define EXP_C2 -11.54156036f    // -8 * log2(e)

// ---------------------------------------------------------------------------
// Portable PTX helpers
// ---------------------------------------------------------------------------
__device__ __forceinline__ uint32_t smem_to_u32(const void* p) {
    uint32_t a;
    asm("{ .reg .u64 t; cvta.to.shared.u64 t, %1; cvt.u32.u64 %0, t; }" : "=r"(a) : "l"(p));
    return a;
}
__device__ __forceinline__ void ldmatrix_x4(uint32_t* r, uint32_t addr) {
    asm volatile("ldmatrix.sync.aligned.m8n8.x4.shared.b16 {%0,%1,%2,%3}, [%4];"
        : "=r"(r[0]), "=r"(r[1]), "=r"(r[2]), "=r"(r[3]) : "r"(addr));
}
__device__ __forceinline__ void mma_fp16(float* c, const uint32_t* a, uint32_t b0, uint32_t b1) {
    asm volatile("mma.sync.aligned.m16n8k16.row.col.f32.f16.f16.f32 "
        "{%0,%1,%2,%3}, {%4,%5,%6,%7}, {%8,%9}, {%0,%1,%2,%3};"
        : "+f"(c[0]), "+f"(c[1]), "+f"(c[2]), "+f"(c[3])
        : "r"(a[0]), "r"(a[1]), "r"(a[2]), "r"(a[3]), "r"(b0), "r"(b1));
}
#define CP_ASYNC16(dst, src) \
    asm volatile("cp.async.cg.shared.global [%0], [%1], 16;" :: "r"(dst), "l"(src) : "memory")
#define CP_COMMIT() asm volatile("cp.async.commit_group;" ::: "memory")
#define CP_WAIT1()  asm volatile("cp.async.wait_group 1;" ::: "memory")

// ===========================================================================
// Tile loaders (K-major fp16, 64 cols = 128 B/row, swizzle c ^= r&7)
// ===========================================================================
__device__ __forceinline__ void load_tile64h(uint32_t dst, const __half* __restrict__ src,
                                             int ldK, int tid) {
#pragma unroll
    for (int i = 0; i < 4; i++) {
        int idx = tid + i * 256;
        int r = idx >> 3, c = idx & 7;
        int sc = c ^ (r & 7);
        CP_ASYNC16(dst + r * 128 + (sc << 4), src + (size_t)r * ldK + c * 8);
    }
}
__device__ __forceinline__ void load_tile64x64h(uint32_t dst, const __half* __restrict__ src,
                                                int ldK, int tid) {
#pragma unroll
    for (int i = 0; i < 2; i++) {
        int idx = tid + i * 256;
        int r = idx >> 3, c = idx & 7;
        int sc = c ^ (r & 7);
        CP_ASYNC16(dst + r * 128 + (sc << 4), src + (size_t)r * ldK + c * 8);
    }
}

// ===========================================================================
// Kernel A: 128x128 fp16 GEMM (C fp16) — M1 only (tiny)
// ===========================================================================
constexpr int H_TILE = 16384;
constexpr int H_OFF_A = 0, H_OFF_B = H_TILE;
constexpr int H_STG = 2 * H_TILE;
constexpr int H_NSTAGE = 3;
constexpr int H_SMEM = H_NSTAGE * H_STG;     // 96 KB

__global__ void __launch_bounds__(256, 1)
hgemm128(const __half* __restrict__ A, const __half* __restrict__ B,
         __half* __restrict__ Ch, int M, int N, int K)
{
    extern __shared__ __align__(1024) char smem[];
    const uint32_t sb = smem_to_u32(smem);
    const int tid  = threadIdx.x;
    const int lane = tid & 31;
    const int wid  = tid >> 5;
    const int wm   = wid & 1;
    const int wn   = wid >> 1;
    const int m0   = blockIdx.y * 128, n0 = blockIdx.x * 128;

    const __half* Ar = A + (size_t)m0 * K;
    const __half* Br = B + (size_t)n0 * K;

    float acc[4][4][4];
#pragma unroll
    for (int i = 0; i < 4; i++)
#pragma unroll
        for (int j = 0; j < 4; j++)
#pragma unroll
            for (int t = 0; t < 4; t++) acc[i][j][t] = 0.f;

    const int NK = K >> 6;

#pragma unroll
    for (int i = 0; i < H_NSTAGE - 1; i++) {
        if (i < NK) {
            uint32_t st = sb + i * H_STG;
            int ko = i * 64;
            load_tile64h(st + H_OFF_A, Ar + ko, K, tid);
            load_tile64h(st + H_OFF_B, Br + ko, K, tid);
        }
        CP_COMMIT();
    }

    const int lr = lane & 15;
    const int lc = lane >> 4;

    for (int k = 0; k < NK; k++) {
        CP_WAIT1();
        __syncthreads();

        int kn = k + H_NSTAGE - 1;
        if (kn < NK) {
            uint32_t st = sb + (kn % H_NSTAGE) * H_STG;
            int ko = kn * 64;
            load_tile64h(st + H_OFF_A, Ar + ko, K, tid);
            load_tile64h(st + H_OFF_B, Br + ko, K, tid);
        }
        CP_COMMIT();

        const uint32_t s = sb + (k % H_NSTAGE) * H_STG;
#pragma unroll
        for (int ks = 0; ks < 4; ks++) {
            uint32_t af[4][4], bfr[2][4];
#pragma unroll
            for (int mi = 0; mi < 4; mi++) {
                int r = wm * 64 + mi * 16 + lr;
                int c = ks * 2 + lc;
                int sc = c ^ (r & 7);
                ldmatrix_x4(af[mi], s + H_OFF_A + r * 128 + (sc << 4));
            }
#pragma unroll
            for (int nj = 0; nj < 2; nj++) {
                int r = wn * 32 + nj * 16 + lr;
                int c = ks * 2 + lc;
                int sc = c ^ (r & 7);
                ldmatrix_x4(bfr[nj], s + H_OFF_B + r * 128 + (sc << 4));
            }
#pragma unroll
            for (int mi = 0; mi < 4; mi++)
#pragma unroll
                for (int ni = 0; ni < 4; ni++) {
                    int nj = ni >> 1, hl = ni & 1;
                    mma_fp16(acc[mi][ni], af[mi], bfr[nj][hl], bfr[nj][2 + hl]);
                }
        }
    }

    const int er = (lane >> 2);
    const int ec = (lane & 3) * 2;
#pragma unroll
    for (int mi = 0; mi < 4; mi++)
#pragma unroll
        for (int ni = 0; ni < 4; ni++) {
            int row = m0 + wm * 64 + mi * 16 + er;
            int col = n0 + wn * 32 + ni * 8 + ec;
#pragma unroll
            for (int h = 0; h < 2; h++) {
                size_t off = (size_t)(row + 8 * h) * N + col;
                *reinterpret_cast<__half2*>(Ch + off) =
                    __floats2half2_rn(acc[mi][ni][2 * h], acc[mi][ni][2 * h + 1]);
            }
        }
}

// ===========================================================================
// Kernel B: 64x128 fp16 GEMM, 2 CTAs/SM — A2/Vt (MODE 1), QK (2), PV (3)
// ===========================================================================
constexpr int S64_OFF_A = 0, S64_OFF_B = 8192;    // A 8 KB, B 16 KB
constexpr int S64_STG = 24576;
constexpr int S64_NSTAGE = 3;
constexpr int S64_SMEM = S64_NSTAGE * S64_STG;    // 72 KB

template <int MODE>
__global__ void __launch_bounds__(256, 2)
hgemm64(const __half* __restrict__ A, const __half* __restrict__ B,
        float* __restrict__ Cf, __half* __restrict__ Ch,
        float* __restrict__ rowsum, int M, int N, int K)
{
    extern __shared__ __align__(1024) char smem[];
    const uint32_t sb = smem_to_u32(smem);
    const int tid  = threadIdx.x;
    const int lane = tid & 31;
    const int wid  = tid >> 5;
    const int wm   = wid & 1;     // 2 warp rows (32 rows each)
    const int wn   = wid >> 1;    // 4 warp cols (32 cols each)
    const int m0   = blockIdx.y * 64, n0 = blockIdx.x * 128;

    const __half* Ar = A + (size_t)m0 * K;
    const __half* Br = B + (size_t)n0 * K;

    float acc[2][4][4];
#pragma unroll
    for (int i = 0; i < 2; i++)
#pragma unroll
        for (int j = 0; j < 4; j++)
#pragma unroll
            for (int t = 0; t < 4; t++) acc[i][j][t] = 0.f;

    const int NK = K >> 6;

#pragma unroll
    for (int i = 0; i < S64_NSTAGE - 1; i++) {
        if (i < NK) {
            uint32_t st = sb + i * S64_STG;
            int ko = i * 64;
            load_tile64x64h(st + S64_OFF_A, Ar + ko, K, tid);
            load_tile64h(st + S64_OFF_B, Br + ko, K, tid);
        }
        CP_COMMIT();
    }

    const int lr = lane & 15;
    const int lc = lane >> 4;

    for (int k = 0; k < NK; k++) {
        CP_WAIT1();
        __syncthreads();

        int kn = k + S64_NSTAGE - 1;
        if (kn < NK) {
            uint32_t st = sb + (kn % S64_NSTAGE) * S64_STG;
            int ko = kn * 64;
            load_tile64x64h(st + S64_OFF_A, Ar + ko, K, tid);
            load_tile64h(st + S64_OFF_B, Br + ko, K, tid);
        }
        CP_COMMIT();

        const uint32_t s = sb + (k % S64_NSTAGE) * S64_STG;
#pragma unroll
        for (int ks = 0; ks < 4; ks++) {
            uint32_t af[2][4], bfr[2][4];
#pragma unroll
            for (int mi = 0; mi < 2; mi++) {
                int r = wm * 32 + mi * 16 + lr;
                int c = ks * 2 + lc;
                int sc = c ^ (r & 7);
                ldmatrix_x4(af[mi], s + S64_OFF_A + r * 128 + (sc << 4));
            }
#pragma unroll
            for (int nj = 0; nj < 2; nj++) {
                int r = wn * 32 + nj * 16 + lr;
                int c = ks * 2 + lc;
                int sc = c ^ (r & 7);
                ldmatrix_x4(bfr[nj], s + S64_OFF_B + r * 128 + (sc << 4));
            }
#pragma unroll
            for (int mi = 0; mi < 2; mi++)
#pragma unroll
                for (int ni = 0; ni < 4; ni++) {
                    int nj = ni >> 1, hl = ni & 1;
                    mma_fp16(acc[mi][ni], af[mi], bfr[nj][hl], bfr[nj][2 + hl]);
                }
        }
    }

    const int er = (lane >> 2);
    const int ec = (lane & 3) * 2;
#pragma unroll
    for (int mi = 0; mi < 2; mi++) {
        float rsum[2] = {0.f, 0.f};
        float rinv[2];
        if (MODE == 3) {
            rinv[0] = 1.0f / rowsum[m0 + wm * 32 + mi * 16 + er];
            rinv[1] = 1.0f / rowsum[m0 + wm * 32 + mi * 16 + er + 8];
        }
#pragma unroll
        for (int ni = 0; ni < 4; ni++) {
            int row = m0 + wm * 32 + mi * 16 + er;
            int col = n0 + wn * 32 + ni * 8 + ec;
#pragma unroll
            for (int h = 0; h < 2; h++) {
                float v0 = acc[mi][ni][2 * h + 0];
                float v1 = acc[mi][ni][2 * h + 1];
                size_t off = (size_t)(row + 8 * h) * N + col;
                if (MODE == 1) {
                    *reinterpret_cast<__half2*>(Ch + off) = __floats2half2_rn(v0, v1);
                } else if (MODE == 2) {
                    float e0 = exp2f(fmaf(v0, EXP_C1, EXP_C2));
                    float e1 = exp2f(fmaf(v1, EXP_C1, EXP_C2));
                    *reinterpret_cast<__half2*>(Ch + off) = __floats2half2_rn(e0, e1);
                    rsum[h] += e0 + e1;
                } else {   // MODE 3
                    *reinterpret_cast<float2*>(Cf + off) =
                        make_float2(v0 * rinv[h], v1 * rinv[h]);
                }
            }
        }
        if (MODE == 2) {
#pragma unroll
            for (int h = 0; h < 2; h++) {
                float v = rsum[h];
                v += __shfl_xor_sync(0xFFFFFFFFu, v, 1);
                v += __shfl_xor_sync(0xFFFFFFFFu, v, 2);
                if ((lane & 3) == 0)
                    atomicAdd(&rowsum[m0 + wm * 32 + mi * 16 + er + 8 * h], v);
            }
        }
    }
}

// ---------------------------------------------------------------------------
// img fp32->fp16 + rowsum zeroing
// ---------------------------------------------------------------------------
constexpr int CN_IMG = N_IMG * DIM / 4;
constexpr int CN_RS  = N_IMG / 4;
constexpr int CN_MAIN = CN_IMG + CN_RS;

__global__ void __launch_bounds__(256)
conv_img_k(const float4* __restrict__ img, __half* __restrict__ img16,
           float4* __restrict__ rowsum)
{
    int i = blockIdx.x * blockDim.x + threadIdx.x;
    if (i < CN_IMG) {
        float4 v = img[i];
        __half2* p = reinterpret_cast<__half2*>(img16 + (size_t)i * 4);
        p[0] = __floats2half2_rn(v.x, v.y);
        p[1] = __floats2half2_rn(v.z, v.w);
    } else if (i - CN_IMG < CN_RS) {
        rowsum[i - CN_IMG] = make_float4(0.f, 0.f, 0.f, 0.f);
    }
}

__global__ void __launch_bounds__(256)
conv16_k(const float4* __restrict__ x, __half* __restrict__ y, int n4)
{
    int i = blockIdx.x * blockDim.x + threadIdx.x;
    if (i >= n4) return;
    float4 v = x[i];
    __half2* p = reinterpret_cast<__half2*>(y + (size_t)i * 4);
    p[0] = __floats2half2_rn(v.x, v.y);
    p[1] = __floats2half2_rn(v.z, v.w);
}

// ---------------------------------------------------------------------------
// Wq/Wk fp32 -> fp16 TRANSPOSED (smem tiled); z selects which weight
// ---------------------------------------------------------------------------
__global__ void __launch_bounds__(256)
tconv_k(const float* __restrict__ wq, const float* __restrict__ wk,
        __half* __restrict__ wqT, __half* __restrict__ wkT)
{
    __shared__ float tile[32][33];
    const float* src = blockIdx.z ? wk : wq;
    __half* dst = blockIdx.z ? wkT : wqT;
    int x0 = blockIdx.x * 32;
    int y0 = blockIdx.y * 32;
    int tx = threadIdx.x & 31, ty = threadIdx.x >> 5;
#pragma unroll
    for (int i = 0; i < 4; i++)
        tile[ty + i * 8][tx] = src[(size_t)(y0 + ty + i * 8) * DIM + x0 + tx];
    __syncthreads();
#pragma unroll
    for (int i = 0; i < 4; i++)
        dst[(size_t)(x0 + ty + i * 8) * HDIM + y0 + tx] =
            __float2half_rn(tile[tx][ty + i * 8]);
}

// ---------------------------------------------------------------------------
extern "C" void kernel_launch(void* const* d_in, const int* in_sizes, int n_in,
                              void* d_out, int out_size)
{
    const float* img = (const float*)d_in[0];   // [N_IMG, DIM]
    const float* txt = (const float*)d_in[1];   // [N_TXT, DIM]
    const float* WQ  = (const float*)d_in[2];   // [HDIM, DIM]
    const float* WK  = (const float*)d_in[3];   // [HDIM, DIM]
    const float* WV  = (const float*)d_in[4];   // [DIM, DIM]
    float* out = (float*)d_out;                 // [N_IMG, DIM]

    static bool init_done = false;
    static cudaStream_t sv = nullptr, si = nullptr;
    static cudaEvent_t ev_fork = nullptr, ev_txt = nullptr, ev_join = nullptr, ev_img = nullptr;
    if (!init_done) {
        cudaFuncSetAttribute(hgemm128,   cudaFuncAttributeMaxDynamicSharedMemorySize, H_SMEM);
        cudaFuncSetAttribute(hgemm64<1>, cudaFuncAttributeMaxDynamicSharedMemorySize, S64_SMEM);
        cudaFuncSetAttribute(hgemm64<2>, cudaFuncAttributeMaxDynamicSharedMemorySize, S64_SMEM);
        cudaFuncSetAttribute(hgemm64<3>, cudaFuncAttributeMaxDynamicSharedMemorySize, S64_SMEM);
        cudaStreamCreateWithFlags(&sv, cudaStreamNonBlocking);
        cudaStreamCreateWithFlags(&si, cudaStreamNonBlocking);
        cudaEventCreateWithFlags(&ev_fork, cudaEventDisableTiming);
        cudaEventCreateWithFlags(&ev_txt,  cudaEventDisableTiming);
        cudaEventCreateWithFlags(&ev_join, cudaEventDisableTiming);
        cudaEventCreateWithFlags(&ev_img,  cudaEventDisableTiming);
        init_done = true;
    }

    __half *img16, *txt16, *wqT16, *wkT16, *m1t16, *wv16, *q16, *vt16, *p16;
    float *rowsum;
    cudaGetSymbolAddress((void**)&img16, g_img16);
    cudaGetSymbolAddress((void**)&txt16, g_txt16);
    cudaGetSymbolAddress((void**)&wqT16, g_wqT16);
    cudaGetSymbolAddress((void**)&wkT16, g_wkT16);
    cudaGetSymbolAddress((void**)&m1t16, g_m1t16);
    cudaGetSymbolAddress((void**)&wv16, g_wv16);
    cudaGetSymbolAddress((void**)&q16, g_q16);
    cudaGetSymbolAddress((void**)&vt16, g_vt16);
    cudaGetSymbolAddress((void**)&p16, g_p16);
    cudaGetSymbolAddress((void**)&rowsum, g_rowsum);

    // ---- fork ----
    cudaEventRecord(ev_fork, 0);
    cudaStreamWaitEvent(sv, ev_fork, 0);
    cudaStreamWaitEvent(si, ev_fork, 0);

    // side stream si: img conv + rowsum zero (overlaps tconv + M1 on main)
    conv_img_k<<<(CN_MAIN + 255) / 256, 256, 0, si>>>(
        (const float4*)img, img16, (float4*)rowsum);
    cudaEventRecord(ev_img, si);

    // side stream sv: txt conv + V chain
    conv16_k<<<(N_TXT * DIM / 4 + 255) / 256, 256, 0, sv>>>(
        (const float4*)txt, txt16, N_TXT * DIM / 4);
    cudaEventRecord(ev_txt, sv);            // main's QK needs txt16
    conv16_k<<<(DIM * DIM / 4 + 255) / 256, 256, 0, sv>>>(
        (const float4*)WV, wv16, DIM * DIM / 4);
    // Vt = WV @ txt^T -> fp16 [DIM, N_TXT]
    hgemm64<1><<<dim3(N_TXT / 128, DIM / 64), 256, S64_SMEM, sv>>>(
        wv16, txt16, nullptr, vt16, nullptr, DIM, N_TXT, DIM);
    cudaEventRecord(ev_join, sv);

    // ---- main stream: weight transposes + M1 (uses only 64 SMs) ----
    tconv_k<<<dim3(DIM / 32, HDIM / 32, 2), 256>>>(WQ, WK, wqT16, wkT16);
    // M1T = wkT @ wqT^T  [DIM, DIM]
    hgemm128<<<dim3(DIM / 128, DIM / 128), 256, H_SMEM>>>(
        wkT16, wqT16, m1t16, DIM, DIM, HDIM);

    // A2 needs img16
    cudaStreamWaitEvent(0, ev_img, 0);
    // A2 = img @ M1 = img @ m1t^T -> fp16 [N_IMG, DIM]
    hgemm64<1><<<dim3(DIM / 128, N_IMG / 64), 256, S64_SMEM>>>(
        img16, m1t16, nullptr, q16, nullptr, N_IMG, DIM, DIM);

    // QK needs txt16 from side stream
    cudaStreamWaitEvent(0, ev_txt, 0);
    // P~ = exp(A2@txt^T / 32 - 8) -> fp16, rowsum via atomics
    hgemm64<2><<<dim3(N_TXT / 128, N_IMG / 64), 256, S64_SMEM>>>(
        q16, txt16, nullptr, p16, rowsum, N_IMG, N_TXT, DIM);

    // ---- join: PV needs vt16 ----
    cudaStreamWaitEvent(0, ev_join, 0);
    // out = (P~ @ Vt^T) / rowsum[row] -> fp32
    hgemm64<3><<<dim3(DIM / 128, N_IMG / 64), 256, S64_SMEM>>>(
        p16, vt16, out, nullptr, rowsum, N_IMG, DIM, N_TXT);
}

// round 14
// speedup vs baseline: 1.5913x; 1.0130x over previous
#include <cuda_runtime.h>
#include <cuda_fp16.h>
#include <cstdint>

#define N_IMG 8192
#define N_TXT 8192
#define DIM   1024
#define HDIM  1024

// ---------------------------------------------------------------------------
// Device scratch (no allocations allowed)
// ---------------------------------------------------------------------------
__device__ __align__(1024) __half g_img16[(size_t)N_IMG * DIM];
__device__ __align__(1024) __half g_txt16[(size_t)N_TXT * DIM];
__device__ __align__(1024) __half g_wqT16[(size_t)DIM * HDIM];     // Wq^T [D,H]
__device__ __align__(1024) __half g_wkT16[(size_t)DIM * HDIM];     // Wk^T [D,H]
__device__ __align__(1024) __half g_m1t16[(size_t)DIM * DIM];      // (Wq^T Wk)^T
__device__ __align__(1024) __half g_wv16 [(size_t)DIM * DIM];      // fp16 WV
__device__ __align__(1024) __half g_q16 [(size_t)N_IMG * HDIM];    // A2 = img @ M1
__device__ __align__(1024) __half g_vt16[(size_t)DIM * N_TXT];
__device__ __align__(1024) __half g_p16 [(size_t)N_IMG * N_TXT];   // 128 MB
__device__ __align__(1024) float  g_rowsum[N_IMG];

// exp constants: exp(s*0.03125 - 8) = exp2(acc*c1 + c2)
#define EXP_C1 0.04508422f      // 0.03125 * log2(e)
#define EXP_C2 -11.54156036f    // -8 * log2(e)

// ---------------------------------------------------------------------------
// Portable PTX helpers
// ---------------------------------------------------------------------------
__device__ __forceinline__ uint32_t smem_to_u32(const void* p) {
    uint32_t a;
    asm("{ .reg .u64 t; cvta.to.shared.u64 t, %1; cvt.u32.u64 %0, t; }" : "=r"(a) : "l"(p));
    return a;
}
__device__ __forceinline__ void ldmatrix_x4(uint32_t* r, uint32_t addr) {
    asm volatile("ldmatrix.sync.aligned.m8n8.x4.shared.b16 {%0,%1,%2,%3}, [%4];"
        : "=r"(r[0]), "=r"(r[1]), "=r"(r[2]), "=r"(r[3]) : "r"(addr));
}
__device__ __forceinline__ void mma_fp16(float* c, const uint32_t* a, uint32_t b0, uint32_t b1) {
    asm volatile("mma.sync.aligned.m16n8k16.row.col.f32.f16.f16.f32 "
        "{%0,%1,%2,%3}, {%4,%5,%6,%7}, {%8,%9}, {%0,%1,%2,%3};"
        : "+f"(c[0]), "+f"(c[1]), "+f"(c[2]), "+f"(c[3])
        : "r"(a[0]), "r"(a[1]), "r"(a[2]), "r"(a[3]), "r"(b0), "r"(b1));
}
#define CP_ASYNC16(dst, src) \
    asm volatile("cp.async.cg.shared.global [%0], [%1], 16;" :: "r"(dst), "l"(src) : "memory")
#define CP_COMMIT() asm volatile("cp.async.commit_group;" ::: "memory")
#define CP_WAIT1()  asm volatile("cp.async.wait_group 1;" ::: "memory")
#define CP_WAIT2()  asm volatile("cp.async.wait_group 2;" ::: "memory")

// ===========================================================================
// Tile loaders (K-major fp16, 64 cols = 128 B/row, swizzle c ^= r&7)
// ===========================================================================
__device__ __forceinline__ void load_tile64h(uint32_t dst, const __half* __restrict__ src,
                                             int ldK, int tid) {
#pragma unroll
    for (int i = 0; i < 4; i++) {
        int idx = tid + i * 256;
        int r = idx >> 3, c = idx & 7;
        int sc = c ^ (r & 7);
        CP_ASYNC16(dst + r * 128 + (sc << 4), src + (size_t)r * ldK + c * 8);
    }
}
__device__ __forceinline__ void load_tile64x64h(uint32_t dst, const __half* __restrict__ src,
                                                int ldK, int tid) {
#pragma unroll
    for (int i = 0; i < 2; i++) {
        int idx = tid + i * 256;
        int r = idx >> 3, c = idx & 7;
        int sc = c ^ (r & 7);
        CP_ASYNC16(dst + r * 128 + (sc << 4), src + (size_t)r * ldK + c * 8);
    }
}

// ===========================================================================
// Kernel A: 128x128 fp16 GEMM (C fp16) — M1 only (tiny)
// ===========================================================================
constexpr int H_TILE = 16384;
constexpr int H_OFF_A = 0, H_OFF_B = H_TILE;
constexpr int H_STG = 2 * H_TILE;
constexpr int H_NSTAGE = 3;
constexpr int H_SMEM = H_NSTAGE * H_STG;     // 96 KB

__global__ void __launch_bounds__(256, 1)
hgemm128(const __half* __restrict__ A, const __half* __restrict__ B,
         __half* __restrict__ Ch, int M, int N, int K)
{
    extern __shared__ __align__(1024) char smem[];
    const uint32_t sb = smem_to_u32(smem);
    const int tid  = threadIdx.x;
    const int lane = tid & 31;
    const int wid  = tid >> 5;
    const int wm   = wid & 1;
    const int wn   = wid >> 1;
    const int m0   = blockIdx.y * 128, n0 = blockIdx.x * 128;

    const __half* Ar = A + (size_t)m0 * K;
    const __half* Br = B + (size_t)n0 * K;

    float acc[4][4][4];
#pragma unroll
    for (int i = 0; i < 4; i++)
#pragma unroll
        for (int j = 0; j < 4; j++)
#pragma unroll
            for (int t = 0; t < 4; t++) acc[i][j][t] = 0.f;

    const int NK = K >> 6;

#pragma unroll
    for (int i = 0; i < H_NSTAGE - 1; i++) {
        if (i < NK) {
            uint32_t st = sb + i * H_STG;
            int ko = i * 64;
            load_tile64h(st + H_OFF_A, Ar + ko, K, tid);
            load_tile64h(st + H_OFF_B, Br + ko, K, tid);
        }
        CP_COMMIT();
    }

    const int lr = lane & 15;
    const int lc = lane >> 4;

    for (int k = 0; k < NK; k++) {
        CP_WAIT1();
        __syncthreads();

        int kn = k + H_NSTAGE - 1;
        if (kn < NK) {
            uint32_t st = sb + (kn % H_NSTAGE) * H_STG;
            int ko = kn * 64;
            load_tile64h(st + H_OFF_A, Ar + ko, K, tid);
            load_tile64h(st + H_OFF_B, Br + ko, K, tid);
        }
        CP_COMMIT();

        const uint32_t s = sb + (k % H_NSTAGE) * H_STG;
#pragma unroll
        for (int ks = 0; ks < 4; ks++) {
            uint32_t af[4][4], bfr[2][4];
#pragma unroll
            for (int mi = 0; mi < 4; mi++) {
                int r = wm * 64 + mi * 16 + lr;
                int c = ks * 2 + lc;
                int sc = c ^ (r & 7);
                ldmatrix_x4(af[mi], s + H_OFF_A + r * 128 + (sc << 4));
            }
#pragma unroll
            for (int nj = 0; nj < 2; nj++) {
                int r = wn * 32 + nj * 16 + lr;
                int c = ks * 2 + lc;
                int sc = c ^ (r & 7);
                ldmatrix_x4(bfr[nj], s + H_OFF_B + r * 128 + (sc << 4));
            }
#pragma unroll
            for (int mi = 0; mi < 4; mi++)
#pragma unroll
                for (int ni = 0; ni < 4; ni++) {
                    int nj = ni >> 1, hl = ni & 1;
                    mma_fp16(acc[mi][ni], af[mi], bfr[nj][hl], bfr[nj][2 + hl]);
                }
        }
    }

    const int er = (lane >> 2);
    const int ec = (lane & 3) * 2;
#pragma unroll
    for (int mi = 0; mi < 4; mi++)
#pragma unroll
        for (int ni = 0; ni < 4; ni++) {
            int row = m0 + wm * 64 + mi * 16 + er;
            int col = n0 + wn * 32 + ni * 8 + ec;
#pragma unroll
            for (int h = 0; h < 2; h++) {
                size_t off = (size_t)(row + 8 * h) * N + col;
                *reinterpret_cast<__half2*>(Ch + off) =
                    __floats2half2_rn(acc[mi][ni][2 * h], acc[mi][ni][2 * h + 1]);
            }
        }
}

// ===========================================================================
// Kernel B: 64x128 fp16 GEMM, 2 CTAs/SM, 4 stages (stage = k & 3)
//   MODE 1: C fp16 (A2, Vt);  MODE 2: exp epilogue (QK);  MODE 3: /rowsum (PV)
// ===========================================================================
constexpr int S64_OFF_A = 0, S64_OFF_B = 8192;    // A 8 KB, B 16 KB
constexpr int S64_STG = 24576;
constexpr int S64_NSTAGE = 4;
constexpr int S64_SMEM = S64_NSTAGE * S64_STG;    // 96 KB (2 CTAs: 192 KB/SM)

template <int MODE>
__global__ void __launch_bounds__(256, 2)
hgemm64(const __half* __restrict__ A, const __half* __restrict__ B,
        float* __restrict__ Cf, __half* __restrict__ Ch,
        float* __restrict__ rowsum, int M, int N, int K)
{
    extern __shared__ __align__(1024) char smem[];
    const uint32_t sb = smem_to_u32(smem);
    const int tid  = threadIdx.x;
    const int lane = tid & 31;
    const int wid  = tid >> 5;
    const int wm   = wid & 1;     // 2 warp rows (32 rows each)
    const int wn   = wid >> 1;    // 4 warp cols (32 cols each)
    const int m0   = blockIdx.y * 64, n0 = blockIdx.x * 128;

    const __half* Ar = A + (size_t)m0 * K;
    const __half* Br = B + (size_t)n0 * K;

    float acc[2][4][4];
#pragma unroll
    for (int i = 0; i < 2; i++)
#pragma unroll
        for (int j = 0; j < 4; j++)
#pragma unroll
            for (int t = 0; t < 4; t++) acc[i][j][t] = 0.f;

    const int NK = K >> 6;

    // prologue: 3 stages in flight
#pragma unroll
    for (int i = 0; i < S64_NSTAGE - 1; i++) {
        if (i < NK) {
            uint32_t st = sb + i * S64_STG;
            int ko = i * 64;
            load_tile64x64h(st + S64_OFF_A, Ar + ko, K, tid);
            load_tile64h(st + S64_OFF_B, Br + ko, K, tid);
        }
        CP_COMMIT();
    }

    const int lr = lane & 15;
    const int lc = lane >> 4;
    // loop-invariant per-warp fragment base rows
    const uint32_t arow0 = (uint32_t)(wm * 32 + lr) * 128;
    const uint32_t arow1 = arow0 + 16 * 128;
    const uint32_t brow0 = (uint32_t)(wn * 32 + lr) * 128;
    const uint32_t brow1 = brow0 + 16 * 128;
    const int arb0 = (wm * 32 + lr) & 7;          // swizzle row bits (same for +16)
    const int brb0 = (wn * 32 + lr) & 7;

    for (int k = 0; k < NK; k++) {
        CP_WAIT2();
        __syncthreads();

        int kn = k + S64_NSTAGE - 1;
        if (kn < NK) {
            uint32_t st = sb + (kn & 3) * S64_STG;
            int ko = kn * 64;
            load_tile64x64h(st + S64_OFF_A, Ar + ko, K, tid);
            load_tile64h(st + S64_OFF_B, Br + ko, K, tid);
        }
        CP_COMMIT();

        const uint32_t s = sb + (k & 3) * S64_STG;
        const uint32_t sa = s + S64_OFF_A;
        const uint32_t sbb = s + S64_OFF_B;
#pragma unroll
        for (int ks = 0; ks < 4; ks++) {
            const int c = ks * 2 + lc;
            uint32_t af[2][4], bfr[2][4];
            ldmatrix_x4(af[0], sa + arow0 + ((c ^ arb0) << 4));
            ldmatrix_x4(af[1], sa + arow1 + ((c ^ arb0) << 4));
            ldmatrix_x4(bfr[0], sbb + brow0 + ((c ^ brb0) << 4));
            ldmatrix_x4(bfr[1], sbb + brow1 + ((c ^ brb0) << 4));
#pragma unroll
            for (int mi = 0; mi < 2; mi++)
#pragma unroll
                for (int ni = 0; ni < 4; ni++) {
                    int nj = ni >> 1, hl = ni & 1;
                    mma_fp16(acc[mi][ni], af[mi], bfr[nj][hl], bfr[nj][2 + hl]);
                }
        }
    }

    const int er = (lane >> 2);
    const int ec = (lane & 3) * 2;
#pragma unroll
    for (int mi = 0; mi < 2; mi++) {
        float rsum[2] = {0.f, 0.f};
        float rinv[2];
        if (MODE == 3) {
            rinv[0] = 1.0f / rowsum[m0 + wm * 32 + mi * 16 + er];
            rinv[1] = 1.0f / rowsum[m0 + wm * 32 + mi * 16 + er + 8];
        }
#pragma unroll
        for (int ni = 0; ni < 4; ni++) {
            int row = m0 + wm * 32 + mi * 16 + er;
            int col = n0 + wn * 32 + ni * 8 + ec;
#pragma unroll
            for (int h = 0; h < 2; h++) {
                float v0 = acc[mi][ni][2 * h + 0];
                float v1 = acc[mi][ni][2 * h + 1];
                size_t off = (size_t)(row + 8 * h) * N + col;
                if (MODE == 1) {
                    *reinterpret_cast<__half2*>(Ch + off) = __floats2half2_rn(v0, v1);
                } else if (MODE == 2) {
                    float e0 = exp2f(fmaf(v0, EXP_C1, EXP_C2));
                    float e1 = exp2f(fmaf(v1, EXP_C1, EXP_C2));
                    *reinterpret_cast<__half2*>(Ch + off) = __floats2half2_rn(e0, e1);
                    rsum[h] += e0 + e1;
                } else {   // MODE 3
                    *reinterpret_cast<float2*>(Cf + off) =
                        make_float2(v0 * rinv[h], v1 * rinv[h]);
                }
            }
        }
        if (MODE == 2) {
#pragma unroll
            for (int h = 0; h < 2; h++) {
                float v = rsum[h];
                v += __shfl_xor_sync(0xFFFFFFFFu, v, 1);
                v += __shfl_xor_sync(0xFFFFFFFFu, v, 2);
                if ((lane & 3) == 0)
                    atomicAdd(&rowsum[m0 + wm * 32 + mi * 16 + er + 8 * h], v);
            }
        }
    }
}

// ---------------------------------------------------------------------------
// img fp32->fp16 + rowsum zeroing
// ---------------------------------------------------------------------------
constexpr int CN_IMG = N_IMG * DIM / 4;
constexpr int CN_RS  = N_IMG / 4;
constexpr int CN_MAIN = CN_IMG + CN_RS;

__global__ void __launch_bounds__(256)
conv_img_k(const float4* __restrict__ img, __half* __restrict__ img16,
           float4* __restrict__ rowsum)
{
    int i = blockIdx.x * blockDim.x + threadIdx.x;
    if (i < CN_IMG) {
        float4 v = img[i];
        __half2* p = reinterpret_cast<__half2*>(img16 + (size_t)i * 4);
        p[0] = __floats2half2_rn(v.x, v.y);
        p[1] = __floats2half2_rn(v.z, v.w);
    } else if (i - CN_IMG < CN_RS) {
        rowsum[i - CN_IMG] = make_float4(0.f, 0.f, 0.f, 0.f);
    }
}

__global__ void __launch_bounds__(256)
conv16_k(const float4* __restrict__ x, __half* __restrict__ y, int n4)
{
    int i = blockIdx.x * blockDim.x + threadIdx.x;
    if (i >= n4) return;
    float4 v = x[i];
    __half2* p = reinterpret_cast<__half2*>(y + (size_t)i * 4);
    p[0] = __floats2half2_rn(v.x, v.y);
    p[1] = __floats2half2_rn(v.z, v.w);
}

// ---------------------------------------------------------------------------
// Wq/Wk fp32 -> fp16 TRANSPOSED (smem tiled); z selects which weight
// ---------------------------------------------------------------------------
__global__ void __launch_bounds__(256)
tconv_k(const float* __restrict__ wq, const float* __restrict__ wk,
        __half* __restrict__ wqT, __half* __restrict__ wkT)
{
    __shared__ float tile[32][33];
    const float* src = blockIdx.z ? wk : wq;
    __half* dst = blockIdx.z ? wkT : wqT;
    int x0 = blockIdx.x * 32;
    int y0 = blockIdx.y * 32;
    int tx = threadIdx.x & 31, ty = threadIdx.x >> 5;
#pragma unroll
    for (int i = 0; i < 4; i++)
        tile[ty + i * 8][tx] = src[(size_t)(y0 + ty + i * 8) * DIM + x0 + tx];
    __syncthreads();
#pragma unroll
    for (int i = 0; i < 4; i++)
        dst[(size_t)(x0 + ty + i * 8) * HDIM + y0 + tx] =
            __float2half_rn(tile[tx][ty + i * 8]);
}

// ---------------------------------------------------------------------------
extern "C" void kernel_launch(void* const* d_in, const int* in_sizes, int n_in,
                              void* d_out, int out_size)
{
    const float* img = (const float*)d_in[0];   // [N_IMG, DIM]
    const float* txt = (const float*)d_in[1];   // [N_TXT, DIM]
    const float* WQ  = (const float*)d_in[2];   // [HDIM, DIM]
    const float* WK  = (const float*)d_in[3];   // [HDIM, DIM]
    const float* WV  = (const float*)d_in[4];   // [DIM, DIM]
    float* out = (float*)d_out;                 // [N_IMG, DIM]

    static bool init_done = false;
    static cudaStream_t sv = nullptr, si = nullptr;
    static cudaEvent_t ev_fork = nullptr, ev_txt = nullptr, ev_join = nullptr, ev_img = nullptr;
    if (!init_done) {
        cudaFuncSetAttribute(hgemm128,   cudaFuncAttributeMaxDynamicSharedMemorySize, H_SMEM);
        cudaFuncSetAttribute(hgemm64<1>, cudaFuncAttributeMaxDynamicSharedMemorySize, S64_SMEM);
        cudaFuncSetAttribute(hgemm64<2>, cudaFuncAttributeMaxDynamicSharedMemorySize, S64_SMEM);
        cudaFuncSetAttribute(hgemm64<3>, cudaFuncAttributeMaxDynamicSharedMemorySize, S64_SMEM);
        cudaStreamCreateWithFlags(&sv, cudaStreamNonBlocking);
        cudaStreamCreateWithFlags(&si, cudaStreamNonBlocking);
        cudaEventCreateWithFlags(&ev_fork, cudaEventDisableTiming);
        cudaEventCreateWithFlags(&ev_txt,  cudaEventDisableTiming);
        cudaEventCreateWithFlags(&ev_join, cudaEventDisableTiming);
        cudaEventCreateWithFlags(&ev_img,  cudaEventDisableTiming);
        init_done = true;
    }

    __half *img16, *txt16, *wqT16, *wkT16, *m1t16, *wv16, *q16, *vt16, *p16;
    float *rowsum;
    cudaGetSymbolAddress((void**)&img16, g_img16);
    cudaGetSymbolAddress((void**)&txt16, g_txt16);
    cudaGetSymbolAddress((void**)&wqT16, g_wqT16);
    cudaGetSymbolAddress((void**)&wkT16, g_wkT16);
    cudaGetSymbolAddress((void**)&m1t16, g_m1t16);
    cudaGetSymbolAddress((void**)&wv16, g_wv16);
    cudaGetSymbolAddress((void**)&q16, g_q16);
    cudaGetSymbolAddress((void**)&vt16, g_vt16);
    cudaGetSymbolAddress((void**)&p16, g_p16);
    cudaGetSymbolAddress((void**)&rowsum, g_rowsum);

    // ---- fork ----
    cudaEventRecord(ev_fork, 0);
    cudaStreamWaitEvent(sv, ev_fork, 0);
    cudaStreamWaitEvent(si, ev_fork, 0);

    // side stream si: img conv + rowsum zero (overlaps tconv + M1 on main)
    conv_img_k<<<(CN_MAIN + 255) / 256, 256, 0, si>>>(
        (const float4*)img, img16, (float4*)rowsum);
    cudaEventRecord(ev_img, si);

    // side stream sv: txt conv + V chain
    conv16_k<<<(N_TXT * DIM / 4 + 255) / 256, 256, 0, sv>>>(
        (const float4*)txt, txt16, N_TXT * DIM / 4);
    cudaEventRecord(ev_txt, sv);            // main's QK needs txt16
    conv16_k<<<(DIM * DIM / 4 + 255) / 256, 256, 0, sv>>>(
        (const float4*)WV, wv16, DIM * DIM / 4);
    // Vt = WV @ txt^T -> fp16 [DIM, N_TXT]
    hgemm64<1><<<dim3(N_TXT / 128, DIM / 64), 256, S64_SMEM, sv>>>(
        wv16, txt16, nullptr, vt16, nullptr, DIM, N_TXT, DIM);
    cudaEventRecord(ev_join, sv);

    // ---- main stream: weight transposes + M1 ----
    tconv_k<<<dim3(DIM / 32, HDIM / 32, 2), 256>>>(WQ, WK, wqT16, wkT16);
    // M1T = wkT @ wqT^T  [DIM, DIM]
    hgemm128<<<dim3(DIM / 128, DIM / 128), 256, H_SMEM>>>(
        wkT16, wqT16, m1t16, DIM, DIM, HDIM);

    // A2 needs img16
    cudaStreamWaitEvent(0, ev_img, 0);
    // A2 = img @ M1 = img @ m1t^T -> fp16 [N_IMG, DIM]
    hgemm64<1><<<dim3(DIM / 128, N_IMG / 64), 256, S64_SMEM>>>(
        img16, m1t16, nullptr, q16, nullptr, N_IMG, DIM, DIM);

    // QK needs txt16 from side stream
    cudaStreamWaitEvent(0, ev_txt, 0);
    // P~ = exp(A2@txt^T / 32 - 8) -> fp16, rowsum via atomics
    hgemm64<2><<<dim3(N_TXT / 128, N_IMG / 64), 256, S64_SMEM>>>(
        q16, txt16, nullptr, p16, rowsum, N_IMG, N_TXT, DIM);

    // ---- join: PV needs vt16 ----
    cudaStreamWaitEvent(0, ev_join, 0);
    // out = (P~ @ Vt^T) / rowsum[row] -> fp32
    hgemm64<3><<<dim3(DIM / 128, N_IMG / 64), 256, S64_SMEM>>>(
        p16, vt16, out, nullptr, rowsum, N_IMG, DIM, N_TXT);
}

// round 15
// speedup vs baseline: 1.7424x; 1.0950x over previous
#include <cuda_runtime.h>
#include <cuda_fp16.h>
#include <cstdint>

#define N_IMG 8192
#define N_TXT 8192
#define DIM   1024
#define HDIM  1024

// ---------------------------------------------------------------------------
// Device scratch (no allocations allowed)
// ---------------------------------------------------------------------------
__device__ __align__(1024) __half g_img16[(size_t)N_IMG * DIM];
__device__ __align__(1024) __half g_txt16[(size_t)N_TXT * DIM];
__device__ __align__(1024) __half g_wqT16[(size_t)DIM * HDIM];     // Wq^T [D,H]
__device__ __align__(1024) __half g_wkT16[(size_t)DIM * HDIM];     // Wk^T [D,H]
__device__ __align__(1024) __half g_m1t16[(size_t)DIM * DIM];      // (Wq^T Wk)^T
__device__ __align__(1024) __half g_wv16 [(size_t)DIM * DIM];      // fp16 WV
__device__ __align__(1024) __half g_q16 [(size_t)N_IMG * HDIM];    // A2 = img @ M1
__device__ __align__(1024) __half g_vt16[(size_t)DIM * N_TXT];
__device__ __align__(1024) __half g_p16 [(size_t)N_IMG * N_TXT];   // 128 MB
__device__ __align__(1024) float  g_rowsum[N_IMG];

// exp constants: exp(s*0.03125 - 8) = exp2(acc*c1 + c2)
#define EXP_C1 0.04508422f      // 0.03125 * log2(e)
#define EXP_C2 -11.54156036f    // -8 * log2(e)

// ---------------------------------------------------------------------------
// Portable PTX helpers
// ---------------------------------------------------------------------------
__device__ __forceinline__ uint32_t smem_to_u32(const void* p) {
    uint32_t a;
    asm("{ .reg .u64 t; cvta.to.shared.u64 t, %1; cvt.u32.u64 %0, t; }" : "=r"(a) : "l"(p));
    return a;
}
__device__ __forceinline__ void ldmatrix_x4(uint32_t* r, uint32_t addr) {
    asm volatile("ldmatrix.sync.aligned.m8n8.x4.shared.b16 {%0,%1,%2,%3}, [%4];"
        : "=r"(r[0]), "=r"(r[1]), "=r"(r[2]), "=r"(r[3]) : "r"(addr));
}
__device__ __forceinline__ void mma_fp16(float* c, const uint32_t* a, uint32_t b0, uint32_t b1) {
    asm volatile("mma.sync.aligned.m16n8k16.row.col.f32.f16.f16.f32 "
        "{%0,%1,%2,%3}, {%4,%5,%6,%7}, {%8,%9}, {%0,%1,%2,%3};"
        : "+f"(c[0]), "+f"(c[1]), "+f"(c[2]), "+f"(c[3])
        : "r"(a[0]), "r"(a[1]), "r"(a[2]), "r"(a[3]), "r"(b0), "r"(b1));
}
#define CP_ASYNC16(dst, src) \
    asm volatile("cp.async.cg.shared.global [%0], [%1], 16;" :: "r"(dst), "l"(src) : "memory")
#define CP_COMMIT() asm volatile("cp.async.commit_group;" ::: "memory")
#define CP_WAIT1()  asm volatile("cp.async.wait_group 1;" ::: "memory")

// ===========================================================================
// Tile loaders (K-major fp16, 64 cols = 128 B/row, swizzle c ^= r&7)
// ===========================================================================
__device__ __forceinline__ void load_tile64h(uint32_t dst, const __half* __restrict__ src,
                                             int ldK, int tid) {
#pragma unroll
    for (int i = 0; i < 4; i++) {
        int idx = tid + i * 256;
        int r = idx >> 3, c = idx & 7;
        int sc = c ^ (r & 7);
        CP_ASYNC16(dst + r * 128 + (sc << 4), src + (size_t)r * ldK + c * 8);
    }
}
__device__ __forceinline__ void load_tile64x64h(uint32_t dst, const __half* __restrict__ src,
                                                int ldK, int tid) {
#pragma unroll
    for (int i = 0; i < 2; i++) {
        int idx = tid + i * 256;
        int r = idx >> 3, c = idx & 7;
        int sc = c ^ (r & 7);
        CP_ASYNC16(dst + r * 128 + (sc << 4), src + (size_t)r * ldK + c * 8);
    }
}

// ===========================================================================
// Kernel A: 128x128 fp16 GEMM (C fp16) — M1 only (tiny)
// ===========================================================================
constexpr int H_TILE = 16384;
constexpr int H_OFF_A = 0, H_OFF_B = H_TILE;
constexpr int H_STG = 2 * H_TILE;
constexpr int H_NSTAGE = 3;
constexpr int H_SMEM = H_NSTAGE * H_STG;     // 96 KB

__global__ void __launch_bounds__(256, 1)
hgemm128(const __half* __restrict__ A, const __half* __restrict__ B,
         __half* __restrict__ Ch, int M, int N, int K)
{
    extern __shared__ __align__(1024) char smem[];
    const uint32_t sb = smem_to_u32(smem);
    const int tid  = threadIdx.x;
    const int lane = tid & 31;
    const int wid  = tid >> 5;
    const int wm   = wid & 1;
    const int wn   = wid >> 1;
    const int m0   = blockIdx.y * 128, n0 = blockIdx.x * 128;

    const __half* Ar = A + (size_t)m0 * K;
    const __half* Br = B + (size_t)n0 * K;

    float acc[4][4][4];
#pragma unroll
    for (int i = 0; i < 4; i++)
#pragma unroll
        for (int j = 0; j < 4; j++)
#pragma unroll
            for (int t = 0; t < 4; t++) acc[i][j][t] = 0.f;

    const int NK = K >> 6;

#pragma unroll
    for (int i = 0; i < H_NSTAGE - 1; i++) {
        if (i < NK) {
            uint32_t st = sb + i * H_STG;
            int ko = i * 64;
            load_tile64h(st + H_OFF_A, Ar + ko, K, tid);
            load_tile64h(st + H_OFF_B, Br + ko, K, tid);
        }
        CP_COMMIT();
    }

    const int lr = lane & 15;
    const int lc = lane >> 4;

    for (int k = 0; k < NK; k++) {
        CP_WAIT1();
        __syncthreads();

        int kn = k + H_NSTAGE - 1;
        if (kn < NK) {
            uint32_t st = sb + (kn % H_NSTAGE) * H_STG;
            int ko = kn * 64;
            load_tile64h(st + H_OFF_A, Ar + ko, K, tid);
            load_tile64h(st + H_OFF_B, Br + ko, K, tid);
        }
        CP_COMMIT();

        const uint32_t s = sb + (k % H_NSTAGE) * H_STG;
#pragma unroll
        for (int ks = 0; ks < 4; ks++) {
            uint32_t af[4][4], bfr[2][4];
#pragma unroll
            for (int mi = 0; mi < 4; mi++) {
                int r = wm * 64 + mi * 16 + lr;
                int c = ks * 2 + lc;
                int sc = c ^ (r & 7);
                ldmatrix_x4(af[mi], s + H_OFF_A + r * 128 + (sc << 4));
            }
#pragma unroll
            for (int nj = 0; nj < 2; nj++) {
                int r = wn * 32 + nj * 16 + lr;
                int c = ks * 2 + lc;
                int sc = c ^ (r & 7);
                ldmatrix_x4(bfr[nj], s + H_OFF_B + r * 128 + (sc << 4));
            }
#pragma unroll
            for (int mi = 0; mi < 4; mi++)
#pragma unroll
                for (int ni = 0; ni < 4; ni++) {
                    int nj = ni >> 1, hl = ni & 1;
                    mma_fp16(acc[mi][ni], af[mi], bfr[nj][hl], bfr[nj][2 + hl]);
                }
        }
    }

    const int er = (lane >> 2);
    const int ec = (lane & 3) * 2;
#pragma unroll
    for (int mi = 0; mi < 4; mi++)
#pragma unroll
        for (int ni = 0; ni < 4; ni++) {
            int row = m0 + wm * 64 + mi * 16 + er;
            int col = n0 + wn * 32 + ni * 8 + ec;
#pragma unroll
            for (int h = 0; h < 2; h++) {
                size_t off = (size_t)(row + 8 * h) * N + col;
                *reinterpret_cast<__half2*>(Ch + off) =
                    __floats2half2_rn(acc[mi][ni][2 * h], acc[mi][ni][2 * h + 1]);
            }
        }
}

// ===========================================================================
// Kernel B: 64x128 fp16 GEMM, 3 CTAs/SM, 3 stages (rolling smem offsets)
//   MODE 1: C fp16 (A2, Vt);  MODE 2: exp epilogue (QK);  MODE 3: /rowsum (PV)
// ===========================================================================
constexpr int S64_OFF_A = 0, S64_OFF_B = 8192;    // A 8 KB, B 16 KB
constexpr int S64_STG = 24576;
constexpr int S64_NSTAGE = 3;
constexpr int S64_SMEM = S64_NSTAGE * S64_STG;    // 72 KB (3 CTAs: 216 KB/SM)

template <int MODE>
__global__ void __launch_bounds__(256, 3)
hgemm64(const __half* __restrict__ A, const __half* __restrict__ B,
        float* __restrict__ Cf, __half* __restrict__ Ch,
        float* __restrict__ rowsum, int M, int N, int K)
{
    extern __shared__ __align__(1024) char smem[];
    const uint32_t sb = smem_to_u32(smem);
    const int tid  = threadIdx.x;
    const int lane = tid & 31;
    const int wid  = tid >> 5;
    const int wm   = wid & 1;     // 2 warp rows (32 rows each)
    const int wn   = wid >> 1;    // 4 warp cols (32 cols each)
    const int m0   = blockIdx.y * 64, n0 = blockIdx.x * 128;

    // rolling global pointers (advance by 64 each chunk; no kn*64 mults)
    const __half* Aw = A + (size_t)m0 * K;   // write-side (prefetch) pointer
    const __half* Bw = B + (size_t)n0 * K;

    float acc[2][4][4];
#pragma unroll
    for (int i = 0; i < 2; i++)
#pragma unroll
        for (int j = 0; j < 4; j++)
#pragma unroll
            for (int t = 0; t < 4; t++) acc[i][j][t] = 0.f;

    const int NK = K >> 6;

    // prologue: stages 0,1 in flight
#pragma unroll
    for (int i = 0; i < S64_NSTAGE - 1; i++) {
        if (i < NK) {
            uint32_t st = sb + i * S64_STG;
            load_tile64x64h(st + S64_OFF_A, Aw, K, tid);
            load_tile64h(st + S64_OFF_B, Bw, K, tid);
            Aw += 64; Bw += 64;
        }
        CP_COMMIT();
    }

    const int lr = lane & 15;
    const int lc = lane >> 4;
    // loop-invariant per-warp fragment bases
    const uint32_t arow0 = (uint32_t)(wm * 32 + lr) * 128 + S64_OFF_A;
    const uint32_t brow0 = (uint32_t)(wn * 32 + lr) * 128 + S64_OFF_B;
    const int arb0 = (wm * 32 + lr) & 7;
    const int brb0 = (wn * 32 + lr) & 7;

    // rolling smem stage offsets
    uint32_t rd = sb;                          // stage being computed
    uint32_t wr = sb + 2 * S64_STG;            // stage being filled
    const uint32_t send = sb + 3 * S64_STG;

    for (int k = 0; k < NK; k++) {
        CP_WAIT1();
        __syncthreads();

        if (k + S64_NSTAGE - 1 < NK) {
            load_tile64x64h(wr + S64_OFF_A, Aw, K, tid);
            load_tile64h(wr + S64_OFF_B, Bw, K, tid);
            Aw += 64; Bw += 64;
        }
        CP_COMMIT();
        wr += S64_STG; if (wr == send) wr = sb;

        const uint32_t sa = rd + arow0;
        const uint32_t sbb = rd + brow0;
#pragma unroll
        for (int ks = 0; ks < 4; ks++) {
            const int c = ks * 2 + lc;
            uint32_t af[2][4], bfr[2][4];
            ldmatrix_x4(af[0], sa + ((c ^ arb0) << 4));
            ldmatrix_x4(af[1], sa + 16 * 128 + ((c ^ arb0) << 4));
            ldmatrix_x4(bfr[0], sbb + ((c ^ brb0) << 4));
            ldmatrix_x4(bfr[1], sbb + 16 * 128 + ((c ^ brb0) << 4));
#pragma unroll
            for (int mi = 0; mi < 2; mi++)
#pragma unroll
                for (int ni = 0; ni < 4; ni++) {
                    int nj = ni >> 1, hl = ni & 1;
                    mma_fp16(acc[mi][ni], af[mi], bfr[nj][hl], bfr[nj][2 + hl]);
                }
        }
        rd += S64_STG; if (rd == send) rd = sb;
    }

    const int er = (lane >> 2);
    const int ec = (lane & 3) * 2;
#pragma unroll
    for (int mi = 0; mi < 2; mi++) {
        float rsum[2] = {0.f, 0.f};
        float rinv[2];
        if (MODE == 3) {
            rinv[0] = 1.0f / rowsum[m0 + wm * 32 + mi * 16 + er];
            rinv[1] = 1.0f / rowsum[m0 + wm * 32 + mi * 16 + er + 8];
        }
#pragma unroll
        for (int ni = 0; ni < 4; ni++) {
            int row = m0 + wm * 32 + mi * 16 + er;
            int col = n0 + wn * 32 + ni * 8 + ec;
#pragma unroll
            for (int h = 0; h < 2; h++) {
                float v0 = acc[mi][ni][2 * h + 0];
                float v1 = acc[mi][ni][2 * h + 1];
                size_t off = (size_t)(row + 8 * h) * N + col;
                if (MODE == 1) {
                    *reinterpret_cast<__half2*>(Ch + off) = __floats2half2_rn(v0, v1);
                } else if (MODE == 2) {
                    float e0 = exp2f(fmaf(v0, EXP_C1, EXP_C2));
                    float e1 = exp2f(fmaf(v1, EXP_C1, EXP_C2));
                    *reinterpret_cast<__half2*>(Ch + off) = __floats2half2_rn(e0, e1);
                    rsum[h] += e0 + e1;
                } else {   // MODE 3
                    *reinterpret_cast<float2*>(Cf + off) =
                        make_float2(v0 * rinv[h], v1 * rinv[h]);
                }
            }
        }
        if (MODE == 2) {
#pragma unroll
            for (int h = 0; h < 2; h++) {
                float v = rsum[h];
                v += __shfl_xor_sync(0xFFFFFFFFu, v, 1);
                v += __shfl_xor_sync(0xFFFFFFFFu, v, 2);
                if ((lane & 3) == 0)
                    atomicAdd(&rowsum[m0 + wm * 32 + mi * 16 + er + 8 * h], v);
            }
        }
    }
}

// ---------------------------------------------------------------------------
// img fp32->fp16 + rowsum zeroing
// ---------------------------------------------------------------------------
constexpr int CN_IMG = N_IMG * DIM / 4;
constexpr int CN_RS  = N_IMG / 4;
constexpr int CN_MAIN = CN_IMG + CN_RS;

__global__ void __launch_bounds__(256)
conv_img_k(const float4* __restrict__ img, __half* __restrict__ img16,
           float4* __restrict__ rowsum)
{
    int i = blockIdx.x * blockDim.x + threadIdx.x;
    if (i < CN_IMG) {
        float4 v = img[i];
        __half2* p = reinterpret_cast<__half2*>(img16 + (size_t)i * 4);
        p[0] = __floats2half2_rn(v.x, v.y);
        p[1] = __floats2half2_rn(v.z, v.w);
    } else if (i - CN_IMG < CN_RS) {
        rowsum[i - CN_IMG] = make_float4(0.f, 0.f, 0.f, 0.f);
    }
}

__global__ void __launch_bounds__(256)
conv16_k(const float4* __restrict__ x, __half* __restrict__ y, int n4)
{
    int i = blockIdx.x * blockDim.x + threadIdx.x;
    if (i >= n4) return;
    float4 v = x[i];
    __half2* p = reinterpret_cast<__half2*>(y + (size_t)i * 4);
    p[0] = __floats2half2_rn(v.x, v.y);
    p[1] = __floats2half2_rn(v.z, v.w);
}

// ---------------------------------------------------------------------------
// Wq/Wk fp32 -> fp16 TRANSPOSED (smem tiled); z selects which weight
// ---------------------------------------------------------------------------
__global__ void __launch_bounds__(256)
tconv_k(const float* __restrict__ wq, const float* __restrict__ wk,
        __half* __restrict__ wqT, __half* __restrict__ wkT)
{
    __shared__ float tile[32][33];
    const float* src = blockIdx.z ? wk : wq;
    __half* dst = blockIdx.z ? wkT : wqT;
    int x0 = blockIdx.x * 32;
    int y0 = blockIdx.y * 32;
    int tx = threadIdx.x & 31, ty = threadIdx.x >> 5;
#pragma unroll
    for (int i = 0; i < 4; i++)
        tile[ty + i * 8][tx] = src[(size_t)(y0 + ty + i * 8) * DIM + x0 + tx];
    __syncthreads();
#pragma unroll
    for (int i = 0; i < 4; i++)
        dst[(size_t)(x0 + ty + i * 8) * HDIM + y0 + tx] =
            __float2half_rn(tile[tx][ty + i * 8]);
}

// ---------------------------------------------------------------------------
extern "C" void kernel_launch(void* const* d_in, const int* in_sizes, int n_in,
                              void* d_out, int out_size)
{
    const float* img = (const float*)d_in[0];   // [N_IMG, DIM]
    const float* txt = (const float*)d_in[1];   // [N_TXT, DIM]
    const float* WQ  = (const float*)d_in[2];   // [HDIM, DIM]
    const float* WK  = (const float*)d_in[3];   // [HDIM, DIM]
    const float* WV  = (const float*)d_in[4];   // [DIM, DIM]
    float* out = (float*)d_out;                 // [N_IMG, DIM]

    static bool init_done = false;
    static cudaStream_t sv = nullptr, si = nullptr;
    static cudaEvent_t ev_fork = nullptr, ev_txt = nullptr, ev_join = nullptr, ev_img = nullptr;
    if (!init_done) {
        cudaFuncSetAttribute(hgemm128,   cudaFuncAttributeMaxDynamicSharedMemorySize, H_SMEM);
        cudaFuncSetAttribute(hgemm64<1>, cudaFuncAttributeMaxDynamicSharedMemorySize, S64_SMEM);
        cudaFuncSetAttribute(hgemm64<2>, cudaFuncAttributeMaxDynamicSharedMemorySize, S64_SMEM);
        cudaFuncSetAttribute(hgemm64<3>, cudaFuncAttributeMaxDynamicSharedMemorySize, S64_SMEM);
        cudaStreamCreateWithFlags(&sv, cudaStreamNonBlocking);
        cudaStreamCreateWithFlags(&si, cudaStreamNonBlocking);
        cudaEventCreateWithFlags(&ev_fork, cudaEventDisableTiming);
        cudaEventCreateWithFlags(&ev_txt,  cudaEventDisableTiming);
        cudaEventCreateWithFlags(&ev_join, cudaEventDisableTiming);
        cudaEventCreateWithFlags(&ev_img,  cudaEventDisableTiming);
        init_done = true;
    }

    __half *img16, *txt16, *wqT16, *wkT16, *m1t16, *wv16, *q16, *vt16, *p16;
    float *rowsum;
    cudaGetSymbolAddress((void**)&img16, g_img16);
    cudaGetSymbolAddress((void**)&txt16, g_txt16);
    cudaGetSymbolAddress((void**)&wqT16, g_wqT16);
    cudaGetSymbolAddress((void**)&wkT16, g_wkT16);
    cudaGetSymbolAddress((void**)&m1t16, g_m1t16);
    cudaGetSymbolAddress((void**)&wv16, g_wv16);
    cudaGetSymbolAddress((void**)&q16, g_q16);
    cudaGetSymbolAddress((void**)&vt16, g_vt16);
    cudaGetSymbolAddress((void**)&p16, g_p16);
    cudaGetSymbolAddress((void**)&rowsum, g_rowsum);

    // ---- fork ----
    cudaEventRecord(ev_fork, 0);
    cudaStreamWaitEvent(sv, ev_fork, 0);
    cudaStreamWaitEvent(si, ev_fork, 0);

    // side stream si: img conv + rowsum zero (overlaps tconv + M1 on main)
    conv_img_k<<<(CN_MAIN + 255) / 256, 256, 0, si>>>(
        (const float4*)img, img16, (float4*)rowsum);
    cudaEventRecord(ev_img, si);

    // side stream sv: txt conv + V chain
    conv16_k<<<(N_TXT * DIM / 4 + 255) / 256, 256, 0, sv>>>(
        (const float4*)txt, txt16, N_TXT * DIM / 4);
    cudaEventRecord(ev_txt, sv);            // main's QK needs txt16
    conv16_k<<<(DIM * DIM / 4 + 255) / 256, 256, 0, sv>>>(
        (const float4*)WV, wv16, DIM * DIM / 4);
    // Vt = WV @ txt^T -> fp16 [DIM, N_TXT]
    hgemm64<1><<<dim3(N_TXT / 128, DIM / 64), 256, S64_SMEM, sv>>>(
        wv16, txt16, nullptr, vt16, nullptr, DIM, N_TXT, DIM);
    cudaEventRecord(ev_join, sv);

    // ---- main stream: weight transposes + M1 ----
    tconv_k<<<dim3(DIM / 32, HDIM / 32, 2), 256>>>(WQ, WK, wqT16, wkT16);
    // M1T = wkT @ wqT^T  [DIM, DIM]
    hgemm128<<<dim3(DIM / 128, DIM / 128), 256, H_SMEM>>>(
        wkT16, wqT16, m1t16, DIM, DIM, HDIM);

    // A2 needs img16
    cudaStreamWaitEvent(0, ev_img, 0);
    // A2 = img @ M1 = img @ m1t^T -> fp16 [N_IMG, DIM]
    hgemm64<1><<<dim3(DIM / 128, N_IMG / 64), 256, S64_SMEM>>>(
        img16, m1t16, nullptr, q16, nullptr, N_IMG, DIM, DIM);

    // QK needs txt16 from side stream
    cudaStreamWaitEvent(0, ev_txt, 0);
    // P~ = exp(A2@txt^T / 32 - 8) -> fp16, rowsum via atomics
    hgemm64<2><<<dim3(N_TXT / 128, N_IMG / 64), 256, S64_SMEM>>>(
        q16, txt16, nullptr, p16, rowsum, N_IMG, N_TXT, DIM);

    // ---- join: PV needs vt16 ----
    cudaStreamWaitEvent(0, ev_join, 0);
    // out = (P~ @ Vt^T) / rowsum[row] -> fp32
    hgemm64<3><<<dim3(DIM / 128, N_IMG / 64), 256, S64_SMEM>>>(
        p16, vt16, out, nullptr, rowsum, N_IMG, DIM, N_TXT);
}